// round 2
// baseline (speedup 1.0000x reference)
#include <cuda_runtime.h>
#include <math.h>
#include <stdint.h>

// Problem constants
#define Hh 256
#define Ll 4
#define Nn 100000
#define Ee 300000
#define BN_EPS 1e-5f
#define AGG_EPS 1e-6f

// ------------------------- static device scratch -------------------------
__device__ float g_x[(size_t)Nn * Hh];
__device__ float g_x2[(size_t)Nn * Hh];
__device__ float g_e[(size_t)Ee * Hh];
__device__ float g_e2[(size_t)Ee * Hh];
__device__ float g_ABDE[(size_t)Nn * 4 * Hh];   // [N,1024]: A|B|D|E
__device__ float g_Ce[(size_t)Ee * Hh];         // Ce -> e_hat -> decoder hidden
__device__ float g_num[(size_t)Nn * Hh];        // num -> xc (in-place)
__device__ float g_den[(size_t)Nn * Hh];
__device__ float g_stats[4 * Hh];               // sum_x, sumsq_x, sum_e, sumsq_e
__device__ float g_wpack[(size_t)Ll * Hh * 4 * Hh];
__device__ float g_bpack[Ll * 4 * Hh];
__device__ float g_fbias[Hh];
__device__ float g_dec1w[528 * Hh];             // zero-padded rows 520..527
__device__ int   g_src[Ee];
__device__ int   g_dst[Ee];
__device__ int   g_idx64;                       // 1 if edge_index is int64

// ------------------------- small prep kernels -------------------------
// Detect int32 vs int64 edge_index: for int64 (values < 2^31), every odd
// 32-bit word is the zero high-half. For int32, odd words are random indices.
__global__ void k_detect_idx(const unsigned int* __restrict__ w) {
    unsigned int s = 0;
    for (int i = threadIdx.x; i < 1024; i += 256) s |= w[2 * i + 1];
#pragma unroll
    for (int off = 16; off; off >>= 1) s |= __shfl_xor_sync(0xFFFFFFFFu, s, off);
    __shared__ unsigned int red[8];
    if ((threadIdx.x & 31) == 0) red[threadIdx.x >> 5] = s;
    __syncthreads();
    if (threadIdx.x == 0) {
        unsigned int t = 0;
        for (int i = 0; i < 8; i++) t |= red[i];
        g_idx64 = (t == 0u) ? 1 : 0;
    }
}

__global__ void k_convert_idx(const void* __restrict__ eidx) {
    int i = blockIdx.x * blockDim.x + threadIdx.x;
    if (i < Ee) {
        if (g_idx64) {
            const long long* p = (const long long*)eidx;
            g_src[i] = (int)p[i];
            g_dst[i] = (int)p[(size_t)Ee + i];
        } else {
            const int* p = (const int*)eidx;
            g_src[i] = p[i];
            g_dst[i] = p[Ee + i];
        }
    }
}

__global__ void k_pack_w(const float* __restrict__ Aw, const float* __restrict__ Bw,
                         const float* __restrict__ Dw, const float* __restrict__ Ew) {
    size_t i = (size_t)blockIdx.x * blockDim.x + threadIdx.x;
    size_t total = (size_t)Ll * Hh * 4 * Hh;
    if (i < total) {
        int j4 = (int)(i % (4 * Hh));
        int k = (int)((i / (4 * Hh)) % Hh);
        int l = (int)(i / ((size_t)4 * Hh * Hh));
        int which = j4 >> 8;
        int j = j4 & 255;
        const float* W = (which == 0) ? Aw : (which == 1) ? Bw : (which == 2) ? Dw : Ew;
        g_wpack[i] = W[(size_t)l * Hh * Hh + (size_t)k * Hh + j];
    }
}

__global__ void k_pack_b(const float* __restrict__ Ab, const float* __restrict__ Bb,
                         const float* __restrict__ Db, const float* __restrict__ Eb) {
    int i = blockIdx.x * blockDim.x + threadIdx.x;
    if (i < Ll * 4 * Hh) {
        int j4 = i % (4 * Hh);
        int l = i / (4 * Hh);
        int which = j4 >> 8;
        int j = j4 & 255;
        const float* B = (which == 0) ? Ab : (which == 1) ? Bb : (which == 2) ? Db : Eb;
        g_bpack[i] = B[l * Hh + j];
    }
}

__global__ void k_fbias(const float* __restrict__ fw, const float* __restrict__ fb) {
    int j = threadIdx.x;
    float s = fb[j];
    for (int k = 0; k < Hh; k++) s += fw[(size_t)k * Hh + j];
    g_fbias[j] = s;
}

__global__ void k_pad_dec1(const float* __restrict__ d1w) {
    int i = blockIdx.x * blockDim.x + threadIdx.x;
    if (i < 528 * Hh) {
        int k = i / Hh, j = i % Hh;
        g_dec1w[i] = (k < 520) ? d1w[(size_t)k * Hh + j] : 0.0f;
    }
}

// ------------------------- tiled fp32 GEMM (64x64x16) -------------------------
template<int RELU>
__global__ __launch_bounds__(256) void gemm64(
    const float* __restrict__ A, const float* __restrict__ B,
    const float* __restrict__ bias, float* __restrict__ C,
    int M, int K, int Nc)
{
    __shared__ float As[16][68];
    __shared__ float Bs[16][68];
    int t = threadIdx.x;
    int tx = t & 15, ty = t >> 4;
    int bm = blockIdx.y * 64, bn = blockIdx.x * 64;

    int ar = t >> 2;            // 0..63 (row in A tile)
    int ac = (t & 3) * 4;       // 0,4,8,12 (col group)
    int br = t >> 4;            // 0..15 (row in B tile)
    int bc = (t & 15) * 4;      // col group
    bool arow_ok = (bm + ar) < M;

    const float* Aptr = A + (size_t)(bm + ar) * K + ac;
    const float* Bptr = B + (size_t)br * Nc + bn + bc;

    float acc[4][4];
#pragma unroll
    for (int i = 0; i < 4; i++)
#pragma unroll
        for (int j = 0; j < 4; j++) acc[i][j] = 0.f;

    for (int k0 = 0; k0 < K; k0 += 16) {
        float4 av = arow_ok ? *(const float4*)Aptr : make_float4(0.f, 0.f, 0.f, 0.f);
        float4 bv = *(const float4*)Bptr;
        As[ac + 0][ar] = av.x; As[ac + 1][ar] = av.y;
        As[ac + 2][ar] = av.z; As[ac + 3][ar] = av.w;
        *(float4*)&Bs[br][bc] = bv;
        __syncthreads();
#pragma unroll
        for (int kk = 0; kk < 16; kk++) {
            float4 a = *(const float4*)&As[kk][ty * 4];
            float4 b = *(const float4*)&Bs[kk][tx * 4];
            acc[0][0] += a.x * b.x; acc[0][1] += a.x * b.y; acc[0][2] += a.x * b.z; acc[0][3] += a.x * b.w;
            acc[1][0] += a.y * b.x; acc[1][1] += a.y * b.y; acc[1][2] += a.y * b.z; acc[1][3] += a.y * b.w;
            acc[2][0] += a.z * b.x; acc[2][1] += a.z * b.y; acc[2][2] += a.z * b.z; acc[2][3] += a.z * b.w;
            acc[3][0] += a.w * b.x; acc[3][1] += a.w * b.y; acc[3][2] += a.w * b.z; acc[3][3] += a.w * b.w;
        }
        __syncthreads();
        Aptr += 16;
        Bptr += (size_t)16 * Nc;
    }

#pragma unroll
    for (int i = 0; i < 4; i++) {
        int m = bm + ty * 4 + i;
        if (m < M) {
#pragma unroll
            for (int j = 0; j < 4; j++) {
                int n = bn + tx * 4 + j;
                float v = acc[i][j] + bias[n];
                if (RELU) v = fmaxf(v, 0.f);
                C[(size_t)m * Nc + n] = v;
            }
        }
    }
}

// Decoder-1 gather-GEMM: A row e = [x[src[e]] (256) | x[dst[e]] (256) | af[e] (8) | pad(8)]
__global__ __launch_bounds__(256) void gemm_dec1(
    const float* __restrict__ xf, const float* __restrict__ af,
    const float* __restrict__ bias, float* __restrict__ C, int M)
{
    const int K = 528, Nc = 256;
    __shared__ float As[16][68];
    __shared__ float Bs[16][68];
    int t = threadIdx.x;
    int tx = t & 15, ty = t >> 4;
    int bm = blockIdx.y * 64, bn = blockIdx.x * 64;

    int ar = t >> 2;
    int ac = (t & 3) * 4;
    int br = t >> 4;
    int bc = (t & 15) * 4;
    int e = bm + ar;
    bool ok = e < M;
    int sN = ok ? g_src[e] : 0;
    int dN = ok ? g_dst[e] : 0;

    const float* Bbase = g_dec1w;
    float acc[4][4];
#pragma unroll
    for (int i = 0; i < 4; i++)
#pragma unroll
        for (int j = 0; j < 4; j++) acc[i][j] = 0.f;

    for (int k0 = 0; k0 < K; k0 += 16) {
        int c0 = k0 + ac;
        float4 av;
        if (!ok || c0 >= 520) av = make_float4(0.f, 0.f, 0.f, 0.f);
        else if (c0 < 256)    av = *(const float4*)&xf[(size_t)sN * Hh + c0];
        else if (c0 < 512)    av = *(const float4*)&xf[(size_t)dN * Hh + (c0 - 256)];
        else                  av = *(const float4*)&af[(size_t)e * 8 + (c0 - 512)];
        float4 bv = *(const float4*)&Bbase[(size_t)(k0 + br) * Nc + bn + bc];
        As[ac + 0][ar] = av.x; As[ac + 1][ar] = av.y;
        As[ac + 2][ar] = av.z; As[ac + 3][ar] = av.w;
        *(float4*)&Bs[br][bc] = bv;
        __syncthreads();
#pragma unroll
        for (int kk = 0; kk < 16; kk++) {
            float4 a = *(const float4*)&As[kk][ty * 4];
            float4 b = *(const float4*)&Bs[kk][tx * 4];
            acc[0][0] += a.x * b.x; acc[0][1] += a.x * b.y; acc[0][2] += a.x * b.z; acc[0][3] += a.x * b.w;
            acc[1][0] += a.y * b.x; acc[1][1] += a.y * b.y; acc[1][2] += a.y * b.z; acc[1][3] += a.y * b.w;
            acc[2][0] += a.z * b.x; acc[2][1] += a.z * b.y; acc[2][2] += a.z * b.z; acc[2][3] += a.z * b.w;
            acc[3][0] += a.w * b.x; acc[3][1] += a.w * b.y; acc[3][2] += a.w * b.z; acc[3][3] += a.w * b.w;
        }
        __syncthreads();
    }

#pragma unroll
    for (int i = 0; i < 4; i++) {
        int m = bm + ty * 4 + i;
        if (m < M) {
#pragma unroll
            for (int j = 0; j < 4; j++) {
                int n = bn + tx * 4 + j;
                float v = fmaxf(acc[i][j] + bias[n], 0.f);
                C[(size_t)m * Nc + n] = v;
            }
        }
    }
}

// ------------------------- edge projection (K=8) -------------------------
__global__ void k_eproj(const float* __restrict__ af, const float* __restrict__ W,
                        const float* __restrict__ b, float* __restrict__ eo) {
    size_t idx = (size_t)blockIdx.x * blockDim.x + threadIdx.x;
    if (idx < (size_t)Ee * Hh) {
        int c = (int)(idx & 255);
        size_t e = idx >> 8;
        float v = b[c];
#pragma unroll
        for (int k = 0; k < 8; k++) v += af[e * 8 + k] * W[k * Hh + c];
        eo[idx] = v;
    }
}

// ------------------------- per-layer edge kernel -------------------------
__global__ __launch_bounds__(256) void k_edge(float* __restrict__ Ce) {
    int c = threadIdx.x;
    int base = blockIdx.x * 32;
    float s = 0.f, sq = 0.f;
    for (int i = 0; i < 32; i++) {
        int e = base + i;
        int sN = g_src[e], dN = g_dst[e];
        float eh = g_ABDE[(size_t)dN * 1024 + 512 + c] +
                   g_ABDE[(size_t)sN * 1024 + 768 + c] +
                   Ce[(size_t)e * Hh + c];
        Ce[(size_t)e * Hh + c] = eh;
        float sg = 1.f / (1.f + expf(-eh));
        atomicAdd(&g_num[(size_t)dN * Hh + c], sg * g_ABDE[(size_t)sN * 1024 + 256 + c]);
        atomicAdd(&g_den[(size_t)dN * Hh + c], sg);
        s += eh; sq += eh * eh;
    }
    atomicAdd(&g_stats[2 * Hh + c], s);
    atomicAdd(&g_stats[3 * Hh + c], sq);
}

__global__ __launch_bounds__(256) void k_node() {
    int c = threadIdx.x;
    int base = blockIdx.x * 32;
    float s = 0.f, sq = 0.f;
    for (int i = 0; i < 32; i++) {
        int n = base + i;
        size_t o = (size_t)n * Hh + c;
        float xc = g_ABDE[(size_t)n * 1024 + c] + g_num[o] / (g_den[o] + AGG_EPS);
        g_num[o] = xc;
        s += xc; sq += xc * xc;
    }
    atomicAdd(&g_stats[c], s);
    atomicAdd(&g_stats[Hh + c], sq);
}

__global__ void k_apply_x(const float* __restrict__ xin, float* __restrict__ xout,
                          const float* __restrict__ gam, const float* __restrict__ bet) {
    size_t idx = (size_t)blockIdx.x * blockDim.x + threadIdx.x;
    if (idx < (size_t)Nn * Hh) {
        int c = (int)(idx & 255);
        float mu = g_stats[c] * (1.f / Nn);
        float var = g_stats[Hh + c] * (1.f / Nn) - mu * mu;
        float v = gam[c] * (g_num[idx] - mu) * rsqrtf(var + BN_EPS) + bet[c];
        xout[idx] = xin[idx] + fmaxf(v, 0.f);
    }
}

__global__ void k_apply_e(const float* __restrict__ ein, const float* __restrict__ ehat,
                          float* __restrict__ eout,
                          const float* __restrict__ gam, const float* __restrict__ bet) {
    size_t idx = (size_t)blockIdx.x * blockDim.x + threadIdx.x;
    if (idx < (size_t)Ee * Hh) {
        int c = (int)(idx & 255);
        float mu = g_stats[2 * Hh + c] * (1.f / Ee);
        float var = g_stats[3 * Hh + c] * (1.f / Ee) - mu * mu;
        float v = gam[c] * (ehat[idx] - mu) * rsqrtf(var + BN_EPS) + bet[c];
        eout[idx] = ein[idx] + fmaxf(v, 0.f);
    }
}

// ------------------------- decoder-2 (H -> 1) -------------------------
__global__ void k_dec2(const float* __restrict__ h, const float* __restrict__ w2,
                       const float* __restrict__ b2, float* __restrict__ out) {
    int e = blockIdx.x * 8 + (threadIdx.x >> 5);
    int lane = threadIdx.x & 31;
    const float4* hp = (const float4*)(h + (size_t)e * Hh);
    const float4* wp = (const float4*)w2;
    float s = 0.f;
#pragma unroll
    for (int i = 0; i < 2; i++) {
        float4 hv = hp[lane * 2 + i];
        float4 wv = wp[lane * 2 + i];
        s += hv.x * wv.x + hv.y * wv.y + hv.z * wv.z + hv.w * wv.w;
    }
#pragma unroll
    for (int off = 16; off; off >>= 1) s += __shfl_xor_sync(0xFFFFFFFFu, s, off);
    if (lane == 0) out[e] = s + b2[0];
}

// ------------------------- host launcher -------------------------
extern "C" void kernel_launch(void* const* d_in, const int* in_sizes, int n_in,
                              void* d_out, int out_size)
{
    // Locate fusion_w (131072 elements = 512*256) to anchor the weight base;
    // handles presence/absence of the num_nodes scalar input.
    int wb = 3;
    for (int i = 3; i < n_in && i < 6; i++) {
        if (in_sizes[i] == 2 * Hh * Hh) { wb = i; break; }
    }

    const void*  eidx = d_in[0];
    const float* af   = (const float*)d_in[1];
    const float* hold = (const float*)d_in[2];
    const float* fw   = (const float*)d_in[wb + 0];
    const float* fb   = (const float*)d_in[wb + 1];
    const float* epw  = (const float*)d_in[wb + 2];
    const float* epb  = (const float*)d_in[wb + 3];
    const float* Aw   = (const float*)d_in[wb + 4];
    const float* Ab   = (const float*)d_in[wb + 5];
    const float* Bw   = (const float*)d_in[wb + 6];
    const float* Bb   = (const float*)d_in[wb + 7];
    const float* Cw   = (const float*)d_in[wb + 8];
    const float* Cb   = (const float*)d_in[wb + 9];
    const float* Dw   = (const float*)d_in[wb + 10];
    const float* Db   = (const float*)d_in[wb + 11];
    const float* Ew   = (const float*)d_in[wb + 12];
    const float* Eb   = (const float*)d_in[wb + 13];
    const float* bxg  = (const float*)d_in[wb + 14];
    const float* bxb  = (const float*)d_in[wb + 15];
    const float* beg  = (const float*)d_in[wb + 16];
    const float* beb  = (const float*)d_in[wb + 17];
    const float* d1w  = (const float*)d_in[wb + 18];
    const float* d1b  = (const float*)d_in[wb + 19];
    const float* d2w  = (const float*)d_in[wb + 20];
    const float* d2b  = (const float*)d_in[wb + 21];

    float *xA, *xB, *eA, *eB, *abde, *ce, *nump, *denp, *statsp, *wpackp, *bpackp, *fbiasp;
    cudaGetSymbolAddress((void**)&xA, g_x);
    cudaGetSymbolAddress((void**)&xB, g_x2);
    cudaGetSymbolAddress((void**)&eA, g_e);
    cudaGetSymbolAddress((void**)&eB, g_e2);
    cudaGetSymbolAddress((void**)&abde, g_ABDE);
    cudaGetSymbolAddress((void**)&ce, g_Ce);
    cudaGetSymbolAddress((void**)&nump, g_num);
    cudaGetSymbolAddress((void**)&denp, g_den);
    cudaGetSymbolAddress((void**)&statsp, g_stats);
    cudaGetSymbolAddress((void**)&wpackp, g_wpack);
    cudaGetSymbolAddress((void**)&bpackp, g_bpack);
    cudaGetSymbolAddress((void**)&fbiasp, g_fbias);

    // --- prep ---
    k_detect_idx<<<1, 256>>>((const unsigned int*)eidx);
    k_convert_idx<<<(Ee + 255) / 256, 256>>>(eidx);
    {
        size_t tw = (size_t)Ll * Hh * 4 * Hh;
        k_pack_w<<<(int)((tw + 255) / 256), 256>>>(Aw, Bw, Dw, Ew);
        k_pack_b<<<(Ll * 4 * Hh + 255) / 256, 256>>>(Ab, Bb, Db, Eb);
        k_fbias<<<1, 256>>>(fw, fb);
        k_pad_dec1<<<(528 * Hh + 255) / 256, 256>>>(d1w);
    }

    // --- node fusion GEMM (ones-concat folded into bias) + edge projection ---
    {
        dim3 grid(Hh / 64, (Nn + 63) / 64);
        gemm64<1><<<grid, 256>>>(hold, fw + (size_t)Hh * Hh, fbiasp, xA, Nn, Hh, Hh);
    }
    k_eproj<<<(int)(((size_t)Ee * Hh + 255) / 256), 256>>>(af, epw, epb, eA);

    float* xin = xA; float* xout = xB;
    float* ein = eA; float* eout = eB;

    for (int l = 0; l < Ll; l++) {
        cudaMemsetAsync(nump, 0, (size_t)Nn * Hh * sizeof(float));
        cudaMemsetAsync(denp, 0, (size_t)Nn * Hh * sizeof(float));
        cudaMemsetAsync(statsp, 0, 4 * Hh * sizeof(float));

        {   // fused A|B|D|E GEMM: [N,256] @ [256,1024]
            dim3 grid(4 * Hh / 64, (Nn + 63) / 64);
            gemm64<0><<<grid, 256>>>(xin, wpackp + (size_t)l * Hh * 4 * Hh,
                                     bpackp + l * 4 * Hh, abde, Nn, Hh, 4 * Hh);
        }
        {   // Ce GEMM: [E,256] @ [256,256]
            dim3 grid(Hh / 64, (Ee + 63) / 64);
            gemm64<0><<<grid, 256>>>(ein, Cw + (size_t)l * Hh * Hh, Cb + l * Hh,
                                     ce, Ee, Hh, Hh);
        }
        k_edge<<<Ee / 32, 256>>>(ce);
        k_node<<<Nn / 32, 256>>>();
        k_apply_x<<<(int)(((size_t)Nn * Hh + 255) / 256), 256>>>(xin, xout, bxg + l * Hh, bxb + l * Hh);
        k_apply_e<<<(int)(((size_t)Ee * Hh + 255) / 256), 256>>>(ein, ce, eout, beg + l * Hh, beb + l * Hh);

        float* t;
        t = xin; xin = xout; xout = t;
        t = ein; ein = eout; eout = t;
    }

    // --- decoder ---
    {
        dim3 grid(Hh / 64, (Ee + 63) / 64);
        gemm_dec1<<<grid, 256>>>(xin, af, d1b, ce, Ee);
    }
    k_dec2<<<Ee / 8, 256>>>(ce, d2w, d2b, (float*)d_out);
}

// round 3
// speedup vs baseline: 1.8725x; 1.8725x over previous
#include <cuda_runtime.h>
#include <cuda_bf16.h>
#include <math.h>
#include <stdint.h>

// Problem constants
#define Hh 256
#define Ll 4
#define Nn 100000
#define Ee 300000
#define BN_EPS 1e-5f
#define AGG_EPS 1e-6f
#define K_DEC 544   // 520 padded to multiple of 32

// ------------------------- static device scratch -------------------------
__device__ float g_x[(size_t)Nn * Hh];
__device__ float g_x2[(size_t)Nn * Hh];
__device__ float g_e[(size_t)Ee * Hh];
__device__ float g_e2[(size_t)Ee * Hh];
__device__ float g_ABDE[(size_t)Nn * 4 * Hh];   // [N,1024]: A|B|D|E
__device__ float g_Ce[(size_t)Ee * Hh];         // Ce -> e_hat -> decoder hidden
__device__ float g_num[(size_t)Nn * Hh];        // num -> xc (in-place)
__device__ float g_den[(size_t)Nn * Hh];
__device__ float g_stats[4 * Hh];               // sum_x, sumsq_x, sum_e, sumsq_e
__device__ float g_bpack[Ll * 4 * Hh];
__device__ float g_fbias[Hh];
__device__ int   g_src[Ee];
__device__ int   g_dst[Ee];
__device__ int   g_idx64;

// split bf16 weights, transposed to [N][K]
__device__ __nv_bfloat16 g_abde_hi[(size_t)Ll * 1024 * 256];
__device__ __nv_bfloat16 g_abde_lo[(size_t)Ll * 1024 * 256];
__device__ __nv_bfloat16 g_c_hi[(size_t)Ll * 256 * 256];
__device__ __nv_bfloat16 g_c_lo[(size_t)Ll * 256 * 256];
__device__ __nv_bfloat16 g_fw_hi[256 * 256];
__device__ __nv_bfloat16 g_fw_lo[256 * 256];
__device__ __nv_bfloat16 g_d1_hi[256 * K_DEC];
__device__ __nv_bfloat16 g_d1_lo[256 * K_DEC];

// ------------------------- small prep kernels -------------------------
__global__ void k_detect_idx(const unsigned int* __restrict__ w) {
    unsigned int s = 0;
    for (int i = threadIdx.x; i < 1024; i += 256) s |= w[2 * i + 1];
#pragma unroll
    for (int off = 16; off; off >>= 1) s |= __shfl_xor_sync(0xFFFFFFFFu, s, off);
    __shared__ unsigned int red[8];
    if ((threadIdx.x & 31) == 0) red[threadIdx.x >> 5] = s;
    __syncthreads();
    if (threadIdx.x == 0) {
        unsigned int t = 0;
        for (int i = 0; i < 8; i++) t |= red[i];
        g_idx64 = (t == 0u) ? 1 : 0;
    }
}

__global__ void k_convert_idx(const void* __restrict__ eidx) {
    int i = blockIdx.x * blockDim.x + threadIdx.x;
    if (i < Ee) {
        if (g_idx64) {
            const long long* p = (const long long*)eidx;
            g_src[i] = (int)p[i];
            g_dst[i] = (int)p[(size_t)Ee + i];
        } else {
            const int* p = (const int*)eidx;
            g_src[i] = p[i];
            g_dst[i] = p[Ee + i];
        }
    }
}

__device__ __forceinline__ void split_write(float v, __nv_bfloat16* hi, __nv_bfloat16* lo, size_t i) {
    __nv_bfloat16 h = __float2bfloat16_rn(v);
    hi[i] = h;
    lo[i] = __float2bfloat16_rn(v - __bfloat162float(h));
}

// ABDE: src W[l][k=256][n=256] x4 mats -> dst [l][n4=1024][k=256]
__global__ void k_split_abde(const float* __restrict__ Aw, const float* __restrict__ Bw,
                             const float* __restrict__ Dw, const float* __restrict__ Ew) {
    size_t i = (size_t)blockIdx.x * 256 + threadIdx.x;
    if (i < (size_t)Ll * 1024 * 256) {
        int k = (int)(i & 255);
        int n = (int)((i >> 8) & 1023);
        int l = (int)(i >> 18);
        const float* W = (n < 256) ? Aw : (n < 512) ? Bw : (n < 768) ? Dw : Ew;
        float v = W[(size_t)l * 65536 + (size_t)k * 256 + (n & 255)];
        split_write(v, g_abde_hi, g_abde_lo, i);
    }
}

// generic: src [K][N] row-major -> dst [N][Kpad] (zero pad k >= K)
__global__ void k_split_gen(const float* __restrict__ src, __nv_bfloat16* __restrict__ hi,
                            __nv_bfloat16* __restrict__ lo, int K, int N, int Kpad) {
    size_t i = (size_t)blockIdx.x * 256 + threadIdx.x;
    if (i < (size_t)N * Kpad) {
        int k = (int)(i % Kpad);
        int n = (int)(i / Kpad);
        float v = (k < K) ? src[(size_t)k * N + n] : 0.0f;
        split_write(v, hi, lo, i);
    }
}

__global__ void k_pack_b(const float* __restrict__ Ab, const float* __restrict__ Bb,
                         const float* __restrict__ Db, const float* __restrict__ Eb) {
    int i = blockIdx.x * blockDim.x + threadIdx.x;
    if (i < Ll * 4 * Hh) {
        int j4 = i % (4 * Hh);
        int l = i / (4 * Hh);
        int which = j4 >> 8;
        int j = j4 & 255;
        const float* B = (which == 0) ? Ab : (which == 1) ? Bb : (which == 2) ? Db : Eb;
        g_bpack[i] = B[l * Hh + j];
    }
}

__global__ void k_fbias(const float* __restrict__ fw, const float* __restrict__ fb) {
    int j = threadIdx.x;
    float s = fb[j];
    for (int k = 0; k < Hh; k++) s += fw[(size_t)k * Hh + j];
    g_fbias[j] = s;
}

// ------------------------- tensor-core machinery -------------------------
__device__ __forceinline__ void mma16816(float* c, const uint32_t* a, const uint32_t* b) {
    asm volatile(
        "mma.sync.aligned.m16n8k16.row.col.f32.bf16.bf16.f32 "
        "{%0,%1,%2,%3}, {%4,%5,%6,%7}, {%8,%9}, {%0,%1,%2,%3};"
        : "+f"(c[0]), "+f"(c[1]), "+f"(c[2]), "+f"(c[3])
        : "r"(a[0]), "r"(a[1]), "r"(a[2]), "r"(a[3]), "r"(b[0]), "r"(b[1]));
}
__device__ __forceinline__ void ldm_x4(uint32_t* r, uint32_t addr) {
    asm volatile("ldmatrix.sync.aligned.m8n8.x4.shared.b16 {%0,%1,%2,%3}, [%4];"
                 : "=r"(r[0]), "=r"(r[1]), "=r"(r[2]), "=r"(r[3]) : "r"(addr));
}
__device__ __forceinline__ void ldm_x2(uint32_t* r, uint32_t addr) {
    asm volatile("ldmatrix.sync.aligned.m8n8.x2.shared.b16 {%0,%1}, [%2];"
                 : "=r"(r[0]), "=r"(r[1]) : "r"(addr));
}

// swizzled byte offset within a [rows][32] bf16 tile (64B rows, 16B chunks)
__device__ __forceinline__ int sw_off(int row, int chunk) {
    return row * 64 + ((chunk ^ ((row >> 1) & 3)) << 4);
}

__device__ __forceinline__ uint32_t pack_bf2(__nv_bfloat16 a, __nv_bfloat16 b) {
    __nv_bfloat162 t = __halves2bfloat162(a, b);
    return *(uint32_t*)&t;
}

// stage A floats (as 4x float4 per thread) split into hi/lo smem tiles
__device__ __forceinline__ void sts_A(const float4* aF, __nv_bfloat16* sAhi, __nv_bfloat16* sAlo,
                                      int a_row, int a_c4) {
#pragma unroll
    for (int i = 0; i < 4; i++) {
        int row = a_row + i * 32;
        int off = sw_off(row, a_c4 >> 1) + ((a_c4 & 1) << 3);
        float4 v = aF[i];
        __nv_bfloat16 h0 = __float2bfloat16_rn(v.x), h1 = __float2bfloat16_rn(v.y);
        __nv_bfloat16 h2 = __float2bfloat16_rn(v.z), h3 = __float2bfloat16_rn(v.w);
        __nv_bfloat16 l0 = __float2bfloat16_rn(v.x - __bfloat162float(h0));
        __nv_bfloat16 l1 = __float2bfloat16_rn(v.y - __bfloat162float(h1));
        __nv_bfloat16 l2 = __float2bfloat16_rn(v.z - __bfloat162float(h2));
        __nv_bfloat16 l3 = __float2bfloat16_rn(v.w - __bfloat162float(h3));
        *(uint2*)((char*)sAhi + off) = make_uint2(pack_bf2(h0, h1), pack_bf2(h2, h3));
        *(uint2*)((char*)sAlo + off) = make_uint2(pack_bf2(l0, l1), pack_bf2(l2, l3));
    }
}

__device__ __forceinline__ void sts_B(const uint4* bhF, const uint4* blF,
                                      __nv_bfloat16* sBhi, __nv_bfloat16* sBlo,
                                      int b_row, int b_ch) {
#pragma unroll
    for (int i = 0; i < 2; i++) {
        int row = b_row + i * 64;
        int off = sw_off(row, b_ch);
        *(uint4*)((char*)sBhi + off) = bhF[i];
        *(uint4*)((char*)sBlo + off) = blF[i];
    }
}

// one BK=32 block-tile worth of mma (3-pass bf16x3)
__device__ __forceinline__ void tile_compute(
    float acc[4][4][4], uint32_t sAhiB, uint32_t sAloB, uint32_t sBhiB, uint32_t sBloB,
    int lane, int wr, int wc) {
#pragma unroll
    for (int kg = 0; kg < 2; kg++) {
        uint32_t ra[4][4], rbh[4][2], rbl[4][2];
#pragma unroll
        for (int tm = 0; tm < 4; tm++) {
            int row = wr * 64 + tm * 16 + (lane & 15);
            int ch = 2 * kg + (lane >> 4);
            ldm_x4(ra[tm], sAhiB + sw_off(row, ch));
        }
#pragma unroll
        for (int tn = 0; tn < 4; tn++) {
            int row = wc * 32 + tn * 8 + (lane & 7);
            int ch = 2 * kg + ((lane >> 3) & 1);
            uint32_t off = sw_off(row, ch);
            ldm_x2(rbh[tn], sBhiB + off);
            ldm_x2(rbl[tn], sBloB + off);
        }
#pragma unroll
        for (int tm = 0; tm < 4; tm++)
#pragma unroll
            for (int tn = 0; tn < 4; tn++) {
                mma16816(acc[tm][tn], ra[tm], rbh[tn]);
                mma16816(acc[tm][tn], ra[tm], rbl[tn]);
            }
#pragma unroll
        for (int tm = 0; tm < 4; tm++) {
            int row = wr * 64 + tm * 16 + (lane & 15);
            int ch = 2 * kg + (lane >> 4);
            ldm_x4(ra[tm], sAloB + sw_off(row, ch));
        }
#pragma unroll
        for (int tm = 0; tm < 4; tm++)
#pragma unroll
            for (int tn = 0; tn < 4; tn++)
                mma16816(acc[tm][tn], ra[tm], rbh[tn]);
    }
}

// ------------------------- bf16x3 GEMM: C = A @ Bt^T + bias -------------------------
// A fp32 [M][K] row-major; B split bf16 [Nc][K]; K % 32 == 0, Nc % 128 == 0
template<int RELU>
__global__ __launch_bounds__(256) void gemm_tc(
    const float* __restrict__ A,
    const __nv_bfloat16* __restrict__ Bhi, const __nv_bfloat16* __restrict__ Blo,
    const float* __restrict__ bias, float* __restrict__ C,
    int M, int K, int Nc)
{
    __shared__ __align__(16) __nv_bfloat16 sAhi[128 * 32];
    __shared__ __align__(16) __nv_bfloat16 sAlo[128 * 32];
    __shared__ __align__(16) __nv_bfloat16 sBhi[128 * 32];
    __shared__ __align__(16) __nv_bfloat16 sBlo[128 * 32];
    uint32_t sAhiB = (uint32_t)__cvta_generic_to_shared(sAhi);
    uint32_t sAloB = (uint32_t)__cvta_generic_to_shared(sAlo);
    uint32_t sBhiB = (uint32_t)__cvta_generic_to_shared(sBhi);
    uint32_t sBloB = (uint32_t)__cvta_generic_to_shared(sBlo);

    int tid = threadIdx.x, lane = tid & 31, w = tid >> 5;
    int wr = w >> 2, wc = w & 3;
    int bm = blockIdx.y * 128, bn = blockIdx.x * 128;

    int a_row = tid >> 3, a_c4 = tid & 7;
    int b_row = tid >> 2, b_ch = tid & 3;

    size_t aOff[4];
#pragma unroll
    for (int i = 0; i < 4; i++) {
        int gr = bm + a_row + i * 32;
        if (gr >= M) gr = M - 1;
        aOff[i] = (size_t)gr * K + a_c4 * 4;
    }
    size_t bOff[2];
#pragma unroll
    for (int i = 0; i < 2; i++)
        bOff[i] = (size_t)(bn + b_row + i * 64) * K + b_ch * 8;

    float acc[4][4][4];
#pragma unroll
    for (int i = 0; i < 4; i++)
#pragma unroll
        for (int j = 0; j < 4; j++)
#pragma unroll
            for (int q = 0; q < 4; q++) acc[i][j][q] = 0.f;

    float4 aF[4]; uint4 bhF[2], blF[2];
#pragma unroll
    for (int i = 0; i < 4; i++) aF[i] = *(const float4*)&A[aOff[i]];
#pragma unroll
    for (int i = 0; i < 2; i++) {
        bhF[i] = *(const uint4*)&Bhi[bOff[i]];
        blF[i] = *(const uint4*)&Blo[bOff[i]];
    }

    for (int k0 = 0; k0 < K; k0 += 32) {
        sts_A(aF, sAhi, sAlo, a_row, a_c4);
        sts_B(bhF, blF, sBhi, sBlo, b_row, b_ch);
        __syncthreads();
        if (k0 + 32 < K) {
#pragma unroll
            for (int i = 0; i < 4; i++) aF[i] = *(const float4*)&A[aOff[i] + k0 + 32];
#pragma unroll
            for (int i = 0; i < 2; i++) {
                bhF[i] = *(const uint4*)&Bhi[bOff[i] + k0 + 32];
                blF[i] = *(const uint4*)&Blo[bOff[i] + k0 + 32];
            }
        }
        tile_compute(acc, sAhiB, sAloB, sBhiB, sBloB, lane, wr, wc);
        __syncthreads();
    }

    int g = lane >> 2, tig = lane & 3;
#pragma unroll
    for (int tm = 0; tm < 4; tm++) {
        int r0 = bm + wr * 64 + tm * 16 + g;
#pragma unroll
        for (int tn = 0; tn < 4; tn++) {
            int col = bn + wc * 32 + tn * 8 + 2 * tig;
            float b0 = bias[col], b1 = bias[col + 1];
            float v0 = acc[tm][tn][0] + b0, v1 = acc[tm][tn][1] + b1;
            float v2 = acc[tm][tn][2] + b0, v3 = acc[tm][tn][3] + b1;
            if (RELU) {
                v0 = fmaxf(v0, 0.f); v1 = fmaxf(v1, 0.f);
                v2 = fmaxf(v2, 0.f); v3 = fmaxf(v3, 0.f);
            }
            if (r0 < M)     { float2 t = {v0, v1}; *(float2*)&C[(size_t)r0 * Nc + col] = t; }
            if (r0 + 8 < M) { float2 t = {v2, v3}; *(float2*)&C[(size_t)(r0 + 8) * Nc + col] = t; }
        }
    }
}

// ------------------------- decoder-1 gather-GEMM (bf16x3) -------------------------
__global__ __launch_bounds__(256) void gemm_dec1_tc(
    const float* __restrict__ xf, const float* __restrict__ af,
    const float* __restrict__ bias, float* __restrict__ C)
{
    const int K = K_DEC, Nc = 256, M = Ee;
    __shared__ __align__(16) __nv_bfloat16 sAhi[128 * 32];
    __shared__ __align__(16) __nv_bfloat16 sAlo[128 * 32];
    __shared__ __align__(16) __nv_bfloat16 sBhi[128 * 32];
    __shared__ __align__(16) __nv_bfloat16 sBlo[128 * 32];
    uint32_t sAhiB = (uint32_t)__cvta_generic_to_shared(sAhi);
    uint32_t sAloB = (uint32_t)__cvta_generic_to_shared(sAlo);
    uint32_t sBhiB = (uint32_t)__cvta_generic_to_shared(sBhi);
    uint32_t sBloB = (uint32_t)__cvta_generic_to_shared(sBlo);

    int tid = threadIdx.x, lane = tid & 31, w = tid >> 5;
    int wr = w >> 2, wc = w & 3;
    int bm = blockIdx.y * 128, bn = blockIdx.x * 128;

    int a_row = tid >> 3, a_c4 = tid & 7;
    int b_row = tid >> 2, b_ch = tid & 3;

    int sN[4], dN[4], eIdx[4];
#pragma unroll
    for (int i = 0; i < 4; i++) {
        int e = bm + a_row + i * 32;
        if (e >= M) e = M - 1;
        eIdx[i] = e; sN[i] = g_src[e]; dN[i] = g_dst[e];
    }
    size_t bOff[2];
#pragma unroll
    for (int i = 0; i < 2; i++)
        bOff[i] = (size_t)(bn + b_row + i * 64) * K + b_ch * 8;

    float acc[4][4][4];
#pragma unroll
    for (int i = 0; i < 4; i++)
#pragma unroll
        for (int j = 0; j < 4; j++)
#pragma unroll
            for (int q = 0; q < 4; q++) acc[i][j][q] = 0.f;

    float4 aF[4]; uint4 bhF[2], blF[2];
    auto gatherA = [&](int k0) {
        int c = k0 + a_c4 * 4;
#pragma unroll
        for (int i = 0; i < 4; i++) {
            float4 v;
            if (c < 256)      v = *(const float4*)&xf[(size_t)sN[i] * Hh + c];
            else if (c < 512) v = *(const float4*)&xf[(size_t)dN[i] * Hh + (c - 256)];
            else if (c < 520) v = *(const float4*)&af[(size_t)eIdx[i] * 8 + (c - 512)];
            else              v = make_float4(0.f, 0.f, 0.f, 0.f);
            aF[i] = v;
        }
    };

    gatherA(0);
#pragma unroll
    for (int i = 0; i < 2; i++) {
        bhF[i] = *(const uint4*)&g_d1_hi[bOff[i]];
        blF[i] = *(const uint4*)&g_d1_lo[bOff[i]];
    }

    for (int k0 = 0; k0 < K; k0 += 32) {
        sts_A(aF, sAhi, sAlo, a_row, a_c4);
        sts_B(bhF, blF, sBhi, sBlo, b_row, b_ch);
        __syncthreads();
        if (k0 + 32 < K) {
            gatherA(k0 + 32);
#pragma unroll
            for (int i = 0; i < 2; i++) {
                bhF[i] = *(const uint4*)&g_d1_hi[bOff[i] + k0 + 32];
                blF[i] = *(const uint4*)&g_d1_lo[bOff[i] + k0 + 32];
            }
        }
        tile_compute(acc, sAhiB, sAloB, sBhiB, sBloB, lane, wr, wc);
        __syncthreads();
    }

    int g = lane >> 2, tig = lane & 3;
#pragma unroll
    for (int tm = 0; tm < 4; tm++) {
        int r0 = bm + wr * 64 + tm * 16 + g;
#pragma unroll
        for (int tn = 0; tn < 4; tn++) {
            int col = bn + wc * 32 + tn * 8 + 2 * tig;
            float b0 = bias[col], b1 = bias[col + 1];
            float v0 = fmaxf(acc[tm][tn][0] + b0, 0.f), v1 = fmaxf(acc[tm][tn][1] + b1, 0.f);
            float v2 = fmaxf(acc[tm][tn][2] + b0, 0.f), v3 = fmaxf(acc[tm][tn][3] + b1, 0.f);
            if (r0 < M)     { float2 t = {v0, v1}; *(float2*)&C[(size_t)r0 * Nc + col] = t; }
            if (r0 + 8 < M) { float2 t = {v2, v3}; *(float2*)&C[(size_t)(r0 + 8) * Nc + col] = t; }
        }
    }
}

// ------------------------- edge projection (K=8) -------------------------
__global__ void k_eproj(const float* __restrict__ af, const float* __restrict__ W,
                        const float* __restrict__ b, float* __restrict__ eo) {
    size_t idx = (size_t)blockIdx.x * blockDim.x + threadIdx.x;
    if (idx < (size_t)Ee * Hh) {
        int c = (int)(idx & 255);
        size_t e = idx >> 8;
        float v = b[c];
#pragma unroll
        for (int k = 0; k < 8; k++) v += af[e * 8 + k] * W[k * Hh + c];
        eo[idx] = v;
    }
}

// ------------------------- per-layer edge/node kernels -------------------------
__global__ __launch_bounds__(256) void k_edge(float* __restrict__ Ce) {
    int c = threadIdx.x;
    int base = blockIdx.x * 32;
    float s = 0.f, sq = 0.f;
    for (int i = 0; i < 32; i++) {
        int e = base + i;
        int sN = g_src[e], dN = g_dst[e];
        float eh = g_ABDE[(size_t)dN * 1024 + 512 + c] +
                   g_ABDE[(size_t)sN * 1024 + 768 + c] +
                   Ce[(size_t)e * Hh + c];
        Ce[(size_t)e * Hh + c] = eh;
        float sg = 1.f / (1.f + expf(-eh));
        atomicAdd(&g_num[(size_t)dN * Hh + c], sg * g_ABDE[(size_t)sN * 1024 + 256 + c]);
        atomicAdd(&g_den[(size_t)dN * Hh + c], sg);
        s += eh; sq += eh * eh;
    }
    atomicAdd(&g_stats[2 * Hh + c], s);
    atomicAdd(&g_stats[3 * Hh + c], sq);
}

__global__ __launch_bounds__(256) void k_node() {
    int c = threadIdx.x;
    int base = blockIdx.x * 32;
    float s = 0.f, sq = 0.f;
    for (int i = 0; i < 32; i++) {
        int n = base + i;
        size_t o = (size_t)n * Hh + c;
        float xc = g_ABDE[(size_t)n * 1024 + c] + g_num[o] / (g_den[o] + AGG_EPS);
        g_num[o] = xc;
        s += xc; sq += xc * xc;
    }
    atomicAdd(&g_stats[c], s);
    atomicAdd(&g_stats[Hh + c], sq);
}

__global__ void k_apply_x(const float* __restrict__ xin, float* __restrict__ xout,
                          const float* __restrict__ gam, const float* __restrict__ bet) {
    size_t idx = (size_t)blockIdx.x * blockDim.x + threadIdx.x;
    if (idx < (size_t)Nn * Hh) {
        int c = (int)(idx & 255);
        float mu = g_stats[c] * (1.f / Nn);
        float var = g_stats[Hh + c] * (1.f / Nn) - mu * mu;
        float v = gam[c] * (g_num[idx] - mu) * rsqrtf(var + BN_EPS) + bet[c];
        xout[idx] = xin[idx] + fmaxf(v, 0.f);
    }
}

__global__ void k_apply_e(const float* __restrict__ ein, const float* __restrict__ ehat,
                          float* __restrict__ eout,
                          const float* __restrict__ gam, const float* __restrict__ bet) {
    size_t idx = (size_t)blockIdx.x * blockDim.x + threadIdx.x;
    if (idx < (size_t)Ee * Hh) {
        int c = (int)(idx & 255);
        float mu = g_stats[2 * Hh + c] * (1.f / Ee);
        float var = g_stats[3 * Hh + c] * (1.f / Ee) - mu * mu;
        float v = gam[c] * (ehat[idx] - mu) * rsqrtf(var + BN_EPS) + bet[c];
        eout[idx] = ein[idx] + fmaxf(v, 0.f);
    }
}

// ------------------------- decoder-2 (H -> 1) -------------------------
__global__ void k_dec2(const float* __restrict__ h, const float* __restrict__ w2,
                       const float* __restrict__ b2, float* __restrict__ out) {
    int e = blockIdx.x * 8 + (threadIdx.x >> 5);
    int lane = threadIdx.x & 31;
    const float4* hp = (const float4*)(h + (size_t)e * Hh);
    const float4* wp = (const float4*)w2;
    float s = 0.f;
#pragma unroll
    for (int i = 0; i < 2; i++) {
        float4 hv = hp[lane * 2 + i];
        float4 wv = wp[lane * 2 + i];
        s += hv.x * wv.x + hv.y * wv.y + hv.z * wv.z + hv.w * wv.w;
    }
#pragma unroll
    for (int off = 16; off; off >>= 1) s += __shfl_xor_sync(0xFFFFFFFFu, s, off);
    if (lane == 0) out[e] = s + b2[0];
}

// ------------------------- host launcher -------------------------
extern "C" void kernel_launch(void* const* d_in, const int* in_sizes, int n_in,
                              void* d_out, int out_size)
{
    int wb = 3;
    for (int i = 3; i < n_in && i < 6; i++) {
        if (in_sizes[i] == 2 * Hh * Hh) { wb = i; break; }
    }

    const void*  eidx = d_in[0];
    const float* af   = (const float*)d_in[1];
    const float* hold = (const float*)d_in[2];
    const float* fw   = (const float*)d_in[wb + 0];
    const float* epw  = (const float*)d_in[wb + 2];
    const float* epb  = (const float*)d_in[wb + 3];
    const float* Aw   = (const float*)d_in[wb + 4];
    const float* Ab   = (const float*)d_in[wb + 5];
    const float* Bw   = (const float*)d_in[wb + 6];
    const float* Bb   = (const float*)d_in[wb + 7];
    const float* Cw   = (const float*)d_in[wb + 8];
    const float* Cb   = (const float*)d_in[wb + 9];
    const float* Dw   = (const float*)d_in[wb + 10];
    const float* Db   = (const float*)d_in[wb + 11];
    const float* Ew   = (const float*)d_in[wb + 12];
    const float* Eb   = (const float*)d_in[wb + 13];
    const float* bxg  = (const float*)d_in[wb + 14];
    const float* bxb  = (const float*)d_in[wb + 15];
    const float* beg  = (const float*)d_in[wb + 16];
    const float* beb  = (const float*)d_in[wb + 17];
    const float* d1w  = (const float*)d_in[wb + 18];
    const float* d1b  = (const float*)d_in[wb + 19];
    const float* d2w  = (const float*)d_in[wb + 20];
    const float* d2b  = (const float*)d_in[wb + 21];

    float *xA, *xB, *eA, *eB, *abde, *ce, *nump, *denp, *statsp, *bpackp, *fbiasp;
    __nv_bfloat16 *abde_hi, *abde_lo, *c_hi, *c_lo, *fw_hi, *fw_lo, *d1_hi, *d1_lo;
    cudaGetSymbolAddress((void**)&xA, g_x);
    cudaGetSymbolAddress((void**)&xB, g_x2);
    cudaGetSymbolAddress((void**)&eA, g_e);
    cudaGetSymbolAddress((void**)&eB, g_e2);
    cudaGetSymbolAddress((void**)&abde, g_ABDE);
    cudaGetSymbolAddress((void**)&ce, g_Ce);
    cudaGetSymbolAddress((void**)&nump, g_num);
    cudaGetSymbolAddress((void**)&denp, g_den);
    cudaGetSymbolAddress((void**)&statsp, g_stats);
    cudaGetSymbolAddress((void**)&bpackp, g_bpack);
    cudaGetSymbolAddress((void**)&fbiasp, g_fbias);
    cudaGetSymbolAddress((void**)&abde_hi, g_abde_hi);
    cudaGetSymbolAddress((void**)&abde_lo, g_abde_lo);
    cudaGetSymbolAddress((void**)&c_hi, g_c_hi);
    cudaGetSymbolAddress((void**)&c_lo, g_c_lo);
    cudaGetSymbolAddress((void**)&fw_hi, g_fw_hi);
    cudaGetSymbolAddress((void**)&fw_lo, g_fw_lo);
    cudaGetSymbolAddress((void**)&d1_hi, g_d1_hi);
    cudaGetSymbolAddress((void**)&d1_lo, g_d1_lo);

    // --- prep ---
    k_detect_idx<<<1, 256>>>((const unsigned int*)eidx);
    k_convert_idx<<<(Ee + 255) / 256, 256>>>(eidx);
    k_pack_b<<<(Ll * 4 * Hh + 255) / 256, 256>>>(Ab, Bb, Db, Eb);
    k_fbias<<<1, 256>>>(fw, Cb - 0 + 0 == nullptr ? nullptr : (const float*)d_in[wb + 1]);
    {
        size_t tw = (size_t)Ll * 1024 * 256;
        k_split_abde<<<(int)((tw + 255) / 256), 256>>>(Aw, Bw, Dw, Ew);
        k_split_gen<<<(256 * 256 + 255) / 256, 256>>>(fw + (size_t)Hh * Hh, fw_hi, fw_lo, 256, 256, 256);
        for (int l = 0; l < Ll; l++)
            k_split_gen<<<(256 * 256 + 255) / 256, 256>>>(Cw + (size_t)l * Hh * Hh,
                                                          c_hi + (size_t)l * Hh * Hh,
                                                          c_lo + (size_t)l * Hh * Hh, 256, 256, 256);
        k_split_gen<<<(256 * K_DEC + 255) / 256, 256>>>(d1w, d1_hi, d1_lo, 520, 256, K_DEC);
    }

    // --- node fusion GEMM + edge projection ---
    {
        dim3 grid(Hh / 128, (Nn + 127) / 128);
        gemm_tc<1><<<grid, 256>>>(hold, fw_hi, fw_lo, fbiasp, xA, Nn, Hh, Hh);
    }
    k_eproj<<<(int)(((size_t)Ee * Hh + 255) / 256), 256>>>(af, epw, epb, eA);

    float* xin = xA; float* xout = xB;
    float* ein = eA; float* eout = eB;

    for (int l = 0; l < Ll; l++) {
        cudaMemsetAsync(nump, 0, (size_t)Nn * Hh * sizeof(float));
        cudaMemsetAsync(denp, 0, (size_t)Nn * Hh * sizeof(float));
        cudaMemsetAsync(statsp, 0, 4 * Hh * sizeof(float));

        {   // fused A|B|D|E GEMM: [N,256] @ [256,1024]
            dim3 grid(4 * Hh / 128, (Nn + 127) / 128);
            gemm_tc<0><<<grid, 256>>>(xin, abde_hi + (size_t)l * 1024 * 256,
                                      abde_lo + (size_t)l * 1024 * 256,
                                      bpackp + l * 4 * Hh, abde, Nn, Hh, 4 * Hh);
        }
        {   // Ce GEMM: [E,256] @ [256,256]
            dim3 grid(Hh / 128, (Ee + 127) / 128);
            gemm_tc<0><<<grid, 256>>>(ein, c_hi + (size_t)l * Hh * Hh,
                                      c_lo + (size_t)l * Hh * Hh,
                                      Cb + l * Hh, ce, Ee, Hh, Hh);
        }
        k_edge<<<Ee / 32, 256>>>(ce);
        k_node<<<Nn / 32, 256>>>();
        k_apply_x<<<(int)(((size_t)Nn * Hh + 255) / 256), 256>>>(xin, xout, bxg + l * Hh, bxb + l * Hh);
        k_apply_e<<<(int)(((size_t)Ee * Hh + 255) / 256), 256>>>(ein, ce, eout, beg + l * Hh, beb + l * Hh);

        float* t;
        t = xin; xin = xout; xout = t;
        t = ein; ein = eout; eout = t;
    }

    // --- decoder ---
    {
        dim3 grid(Hh / 128, (Ee + 127) / 128);
        gemm_dec1_tc<<<grid, 256>>>(xin, af, d1b, ce);
    }
    k_dec2<<<Ee / 8, 256>>>(ce, d2w, d2b, (float*)d_out);
}

// round 4
// speedup vs baseline: 1.9812x; 1.0580x over previous
#include <cuda_runtime.h>
#include <cuda_bf16.h>
#include <math.h>
#include <stdint.h>

// Problem constants
#define Hh 256
#define Ll 4
#define Nn 100000
#define Ee 300000
#define BN_EPS 1e-5f
#define AGG_EPS 1e-6f
#define K_DEC 544   // 520 padded to multiple of 32

// ------------------------- static device scratch -------------------------
__device__ float g_x[(size_t)Nn * Hh];
__device__ float g_x2[(size_t)Nn * Hh];
__device__ float g_e[(size_t)Ee * Hh];
__device__ float g_e2[(size_t)Ee * Hh];
__device__ float g_ABDE[(size_t)Nn * 4 * Hh];   // [N,1024]: A|B|D|E
__device__ float g_Ce[(size_t)Ee * Hh];         // Ce -> e_hat -> decoder hidden
__device__ float g_num[(size_t)Nn * Hh];        // num -> xc (in-place)
__device__ float g_den[(size_t)Nn * Hh];
__device__ float g_stats[4 * Hh];               // sum_x, sumsq_x, sum_e, sumsq_e
__device__ float g_bpack[Ll * 4 * Hh];
__device__ float g_fbias[Hh];
__device__ int   g_src[Ee];
__device__ int   g_dst[Ee];
__device__ int   g_idx64;

// split bf16 weights, transposed to [N][K]
__device__ __nv_bfloat16 g_abde_hi[(size_t)Ll * 1024 * 256];
__device__ __nv_bfloat16 g_abde_lo[(size_t)Ll * 1024 * 256];
__device__ __nv_bfloat16 g_c_hi[(size_t)Ll * 256 * 256];
__device__ __nv_bfloat16 g_c_lo[(size_t)Ll * 256 * 256];
__device__ __nv_bfloat16 g_fw_hi[256 * 256];
__device__ __nv_bfloat16 g_fw_lo[256 * 256];
__device__ __nv_bfloat16 g_d1_hi[256 * K_DEC];
__device__ __nv_bfloat16 g_d1_lo[256 * K_DEC];

// split bf16 activations
__device__ __nv_bfloat16 g_xh[(size_t)Nn * Hh];
__device__ __nv_bfloat16 g_xl[(size_t)Nn * Hh];
__device__ __nv_bfloat16 g_eh[(size_t)Ee * Hh];
__device__ __nv_bfloat16 g_el[(size_t)Ee * Hh];
__device__ __nv_bfloat16 g_hh[(size_t)Nn * Hh];
__device__ __nv_bfloat16 g_hl[(size_t)Nn * Hh];
__device__ __nv_bfloat16 g_afh[(size_t)Ee * 32];
__device__ __nv_bfloat16 g_afl[(size_t)Ee * 32];

// ------------------------- small prep kernels -------------------------
__global__ void k_detect_idx(const unsigned int* __restrict__ w) {
    unsigned int s = 0;
    for (int i = threadIdx.x; i < 1024; i += 256) s |= w[2 * i + 1];
#pragma unroll
    for (int off = 16; off; off >>= 1) s |= __shfl_xor_sync(0xFFFFFFFFu, s, off);
    __shared__ unsigned int red[8];
    if ((threadIdx.x & 31) == 0) red[threadIdx.x >> 5] = s;
    __syncthreads();
    if (threadIdx.x == 0) {
        unsigned int t = 0;
        for (int i = 0; i < 8; i++) t |= red[i];
        g_idx64 = (t == 0u) ? 1 : 0;
    }
}

__global__ void k_convert_idx(const void* __restrict__ eidx) {
    int i = blockIdx.x * blockDim.x + threadIdx.x;
    if (i < Ee) {
        if (g_idx64) {
            const long long* p = (const long long*)eidx;
            g_src[i] = (int)p[i];
            g_dst[i] = (int)p[(size_t)Ee + i];
        } else {
            const int* p = (const int*)eidx;
            g_src[i] = p[i];
            g_dst[i] = p[Ee + i];
        }
    }
}

__device__ __forceinline__ void split_write(float v, __nv_bfloat16* hi, __nv_bfloat16* lo, size_t i) {
    __nv_bfloat16 h = __float2bfloat16_rn(v);
    hi[i] = h;
    lo[i] = __float2bfloat16_rn(v - __bfloat162float(h));
}

// ABDE: src W[l][k=256][n=256] x4 mats -> dst [l][n4=1024][k=256]
__global__ void k_split_abde(const float* __restrict__ Aw, const float* __restrict__ Bw,
                             const float* __restrict__ Dw, const float* __restrict__ Ew) {
    size_t i = (size_t)blockIdx.x * 256 + threadIdx.x;
    if (i < (size_t)Ll * 1024 * 256) {
        int k = (int)(i & 255);
        int n = (int)((i >> 8) & 1023);
        int l = (int)(i >> 18);
        const float* W = (n < 256) ? Aw : (n < 512) ? Bw : (n < 768) ? Dw : Ew;
        float v = W[(size_t)l * 65536 + (size_t)k * 256 + (n & 255)];
        split_write(v, g_abde_hi, g_abde_lo, i);
    }
}

// generic: src [K][N] row-major -> dst [N][Kpad] (zero pad k >= K)
__global__ void k_split_gen(const float* __restrict__ src, __nv_bfloat16* __restrict__ hi,
                            __nv_bfloat16* __restrict__ lo, int K, int N, int Kpad) {
    size_t i = (size_t)blockIdx.x * 256 + threadIdx.x;
    if (i < (size_t)N * Kpad) {
        int k = (int)(i % Kpad);
        int n = (int)(i / Kpad);
        float v = (k < K) ? src[(size_t)k * N + n] : 0.0f;
        split_write(v, hi, lo, i);
    }
}

// plain elementwise split (no transpose)
__global__ void k_split_plain(const float* __restrict__ src, __nv_bfloat16* __restrict__ hi,
                              __nv_bfloat16* __restrict__ lo, size_t total) {
    size_t i = (size_t)blockIdx.x * 256 + threadIdx.x;
    if (i < total) split_write(src[i], hi, lo, i);
}

// af [E][8] -> padded [E][32] hi/lo
__global__ void k_split_af(const float* __restrict__ af) {
    size_t i = (size_t)blockIdx.x * 256 + threadIdx.x;
    if (i < (size_t)Ee * 32) {
        int c = (int)(i & 31);
        size_t e = i >> 5;
        float v = (c < 8) ? af[e * 8 + c] : 0.0f;
        split_write(v, g_afh, g_afl, i);
    }
}

__global__ void k_pack_b(const float* __restrict__ Ab, const float* __restrict__ Bb,
                         const float* __restrict__ Db, const float* __restrict__ Eb) {
    int i = blockIdx.x * blockDim.x + threadIdx.x;
    if (i < Ll * 4 * Hh) {
        int j4 = i % (4 * Hh);
        int l = i / (4 * Hh);
        int which = j4 >> 8;
        int j = j4 & 255;
        const float* B = (which == 0) ? Ab : (which == 1) ? Bb : (which == 2) ? Db : Eb;
        g_bpack[i] = B[l * Hh + j];
    }
}

__global__ void k_fbias(const float* __restrict__ fw, const float* __restrict__ fb) {
    int j = threadIdx.x;
    float s = fb[j];
    for (int k = 0; k < Hh; k++) s += fw[(size_t)k * Hh + j];
    g_fbias[j] = s;
}

// ------------------------- tensor-core machinery -------------------------
__device__ __forceinline__ void mma16816(float* c, const uint32_t* a, const uint32_t* b) {
    asm volatile(
        "mma.sync.aligned.m16n8k16.row.col.f32.bf16.bf16.f32 "
        "{%0,%1,%2,%3}, {%4,%5,%6,%7}, {%8,%9}, {%0,%1,%2,%3};"
        : "+f"(c[0]), "+f"(c[1]), "+f"(c[2]), "+f"(c[3])
        : "r"(a[0]), "r"(a[1]), "r"(a[2]), "r"(a[3]), "r"(b[0]), "r"(b[1]));
}
__device__ __forceinline__ void ldm_x4(uint32_t* r, uint32_t addr) {
    asm volatile("ldmatrix.sync.aligned.m8n8.x4.shared.b16 {%0,%1,%2,%3}, [%4];"
                 : "=r"(r[0]), "=r"(r[1]), "=r"(r[2]), "=r"(r[3]) : "r"(addr));
}
__device__ __forceinline__ void ldm_x2(uint32_t* r, uint32_t addr) {
    asm volatile("ldmatrix.sync.aligned.m8n8.x2.shared.b16 {%0,%1}, [%2];"
                 : "=r"(r[0]), "=r"(r[1]) : "r"(addr));
}
__device__ __forceinline__ void cpa16(uint32_t s, const void* g) {
    asm volatile("cp.async.cg.shared.global [%0], [%1], 16;" :: "r"(s), "l"(g));
}
__device__ __forceinline__ void cpa_commit() {
    asm volatile("cp.async.commit_group;");
}
__device__ __forceinline__ void cpa_wait0() {
    asm volatile("cp.async.wait_group 0;" ::: "memory");
}

// swizzled byte offset within a [rows][32] bf16 tile (64B rows, 16B chunks)
__device__ __forceinline__ int sw_off(int row, int chunk) {
    return row * 64 + ((chunk ^ ((row >> 1) & 3)) << 4);
}

// smem stage layout (bytes): Ahi +0, Alo +8192, Bhi +16384, Blo +24576; stage stride 32768
#define ST_ALO 8192
#define ST_BHI 16384
#define ST_BLO 24576
#define ST_STRIDE 32768

// one BK=32 block-tile worth of mma (3-pass bf16x3)
__device__ __forceinline__ void tile_compute(
    float acc[4][4][4], uint32_t sbase, int lane, int wr, int wc) {
    uint32_t sAhiB = sbase, sAloB = sbase + ST_ALO, sBhiB = sbase + ST_BHI, sBloB = sbase + ST_BLO;
#pragma unroll
    for (int kg = 0; kg < 2; kg++) {
        uint32_t ra[4][4], rbh[4][2], rbl[4][2];
#pragma unroll
        for (int tm = 0; tm < 4; tm++) {
            int row = wr * 64 + tm * 16 + (lane & 15);
            int ch = 2 * kg + (lane >> 4);
            ldm_x4(ra[tm], sAhiB + sw_off(row, ch));
        }
#pragma unroll
        for (int tn = 0; tn < 4; tn++) {
            int row = wc * 32 + tn * 8 + (lane & 7);
            int ch = 2 * kg + ((lane >> 3) & 1);
            uint32_t off = sw_off(row, ch);
            ldm_x2(rbh[tn], sBhiB + off);
            ldm_x2(rbl[tn], sBloB + off);
        }
#pragma unroll
        for (int tm = 0; tm < 4; tm++)
#pragma unroll
            for (int tn = 0; tn < 4; tn++) {
                mma16816(acc[tm][tn], ra[tm], rbh[tn]);
                mma16816(acc[tm][tn], ra[tm], rbl[tn]);
            }
#pragma unroll
        for (int tm = 0; tm < 4; tm++) {
            int row = wr * 64 + tm * 16 + (lane & 15);
            int ch = 2 * kg + (lane >> 4);
            ldm_x4(ra[tm], sAloB + sw_off(row, ch));
        }
#pragma unroll
        for (int tm = 0; tm < 4; tm++)
#pragma unroll
            for (int tn = 0; tn < 4; tn++)
                mma16816(acc[tm][tn], ra[tm], rbh[tn]);
    }
}

__device__ __forceinline__ uint32_t pack_bf2(float a, float b) {
    __nv_bfloat162 t = __floats2bfloat162_rn(a, b);
    return *(uint32_t*)&t;
}

// ------------------------- bf16x3 GEMM with cp.async pipeline -------------------------
// A split bf16 [M][K]; B split bf16 [Nc][K]; C fp32 [M][Nc].
// EPI: 0 = bias only; 1 = bias+relu; 2 = bias+relu + split-write bf16 hi/lo
template<int EPI>
__global__ __launch_bounds__(256) void gemm_tc2(
    const __nv_bfloat16* __restrict__ Ahi, const __nv_bfloat16* __restrict__ Alo,
    const __nv_bfloat16* __restrict__ Bhi, const __nv_bfloat16* __restrict__ Blo,
    const float* __restrict__ bias, float* __restrict__ C,
    __nv_bfloat16* __restrict__ Chi, __nv_bfloat16* __restrict__ Clo,
    int M, int K, int Nc)
{
    extern __shared__ __align__(16) char smem[];
    uint32_t sbase0 = (uint32_t)__cvta_generic_to_shared(smem);

    int tid = threadIdx.x, lane = tid & 31, w = tid >> 5;
    int wr = w >> 2, wc = w & 3;
    int bm = blockIdx.y * 128, bn = blockIdx.x * 128;

    int r = tid >> 1, ch0 = (tid & 1) * 2;
    int gr = bm + r; if (gr >= M) gr = M - 1;
    size_t aRow = (size_t)gr * K;
    size_t bRow = (size_t)(bn + r) * K;

    float acc[4][4][4];
#pragma unroll
    for (int i = 0; i < 4; i++)
#pragma unroll
        for (int j = 0; j < 4; j++)
#pragma unroll
            for (int q = 0; q < 4; q++) acc[i][j][q] = 0.f;

    auto load_stage = [&](uint32_t sb, int k0) {
#pragma unroll
        for (int i = 0; i < 2; i++) {
            int ch = ch0 + i;
            uint32_t so = sw_off(r, ch);
            size_t go = (size_t)k0 + ch * 8;
            cpa16(sb + so,          Ahi + aRow + go);
            cpa16(sb + ST_ALO + so, Alo + aRow + go);
            cpa16(sb + ST_BHI + so, Bhi + bRow + go);
            cpa16(sb + ST_BLO + so, Blo + bRow + go);
        }
        cpa_commit();
    };

    load_stage(sbase0, 0);
    int cur = 0;
    for (int k0 = 0; k0 < K; k0 += 32) {
        cpa_wait0();
        __syncthreads();
        if (k0 + 32 < K) load_stage(sbase0 + (cur ^ 1) * ST_STRIDE, k0 + 32);
        tile_compute(acc, sbase0 + cur * ST_STRIDE, lane, wr, wc);
        cur ^= 1;
    }

    int g = lane >> 2, tig = lane & 3;
#pragma unroll
    for (int tm = 0; tm < 4; tm++) {
        int r0 = bm + wr * 64 + tm * 16 + g;
#pragma unroll
        for (int tn = 0; tn < 4; tn++) {
            int col = bn + wc * 32 + tn * 8 + 2 * tig;
            float b0 = bias[col], b1 = bias[col + 1];
            float v0 = acc[tm][tn][0] + b0, v1 = acc[tm][tn][1] + b1;
            float v2 = acc[tm][tn][2] + b0, v3 = acc[tm][tn][3] + b1;
            if (EPI >= 1) {
                v0 = fmaxf(v0, 0.f); v1 = fmaxf(v1, 0.f);
                v2 = fmaxf(v2, 0.f); v3 = fmaxf(v3, 0.f);
            }
            if (r0 < M) {
                size_t o = (size_t)r0 * Nc + col;
                float2 t = {v0, v1}; *(float2*)&C[o] = t;
                if (EPI == 2) {
                    __nv_bfloat16 h0 = __float2bfloat16_rn(v0), h1 = __float2bfloat16_rn(v1);
                    *(uint32_t*)&Chi[o] = pack_bf2(v0, v1);
                    *(uint32_t*)&Clo[o] = pack_bf2(v0 - __bfloat162float(h0), v1 - __bfloat162float(h1));
                }
            }
            if (r0 + 8 < M) {
                size_t o = (size_t)(r0 + 8) * Nc + col;
                float2 t = {v2, v3}; *(float2*)&C[o] = t;
                if (EPI == 2) {
                    __nv_bfloat16 h2 = __float2bfloat16_rn(v2), h3 = __float2bfloat16_rn(v3);
                    *(uint32_t*)&Chi[o] = pack_bf2(v2, v3);
                    *(uint32_t*)&Clo[o] = pack_bf2(v2 - __bfloat162float(h2), v3 - __bfloat162float(h3));
                }
            }
        }
    }
}

// ------------------------- decoder-1 gather-GEMM (bf16x3, cp.async) -------------------------
__global__ __launch_bounds__(256) void gemm_dec1_tc(
    const float* __restrict__ bias, float* __restrict__ C)
{
    const int K = K_DEC, Nc = 256, M = Ee;
    extern __shared__ __align__(16) char smem[];
    uint32_t sbase0 = (uint32_t)__cvta_generic_to_shared(smem);

    int tid = threadIdx.x, lane = tid & 31, w = tid >> 5;
    int wr = w >> 2, wc = w & 3;
    int bm = blockIdx.y * 128, bn = blockIdx.x * 128;

    int r = tid >> 1, ch0 = (tid & 1) * 2;
    int e = bm + r; if (e >= M) e = M - 1;
    int sN = g_src[e], dN = g_dst[e];
    size_t bRow = (size_t)(bn + r) * K;

    float acc[4][4][4];
#pragma unroll
    for (int i = 0; i < 4; i++)
#pragma unroll
        for (int j = 0; j < 4; j++)
#pragma unroll
            for (int q = 0; q < 4; q++) acc[i][j][q] = 0.f;

    auto load_stage = [&](uint32_t sb, int k0) {
#pragma unroll
        for (int i = 0; i < 2; i++) {
            int ch = ch0 + i;
            uint32_t so = sw_off(r, ch);
            int c0 = k0 + ch * 8;
            const __nv_bfloat16 *ph, *pl;
            if (c0 < 256)      { ph = g_xh + (size_t)sN * Hh + c0;        pl = g_xl + (size_t)sN * Hh + c0; }
            else if (c0 < 512) { ph = g_xh + (size_t)dN * Hh + (c0-256);  pl = g_xl + (size_t)dN * Hh + (c0-256); }
            else               { ph = g_afh + (size_t)e * 32 + (c0-512);  pl = g_afl + (size_t)e * 32 + (c0-512); }
            cpa16(sb + so,          ph);
            cpa16(sb + ST_ALO + so, pl);
            cpa16(sb + ST_BHI + so, g_d1_hi + bRow + c0);
            cpa16(sb + ST_BLO + so, g_d1_lo + bRow + c0);
        }
        cpa_commit();
    };

    load_stage(sbase0, 0);
    int cur = 0;
    for (int k0 = 0; k0 < K; k0 += 32) {
        cpa_wait0();
        __syncthreads();
        if (k0 + 32 < K) load_stage(sbase0 + (cur ^ 1) * ST_STRIDE, k0 + 32);
        tile_compute(acc, sbase0 + cur * ST_STRIDE, lane, wr, wc);
        cur ^= 1;
    }

    int g = lane >> 2, tig = lane & 3;
#pragma unroll
    for (int tm = 0; tm < 4; tm++) {
        int r0 = bm + wr * 64 + tm * 16 + g;
#pragma unroll
        for (int tn = 0; tn < 4; tn++) {
            int col = bn + wc * 32 + tn * 8 + 2 * tig;
            float b0 = bias[col], b1 = bias[col + 1];
            float v0 = fmaxf(acc[tm][tn][0] + b0, 0.f), v1 = fmaxf(acc[tm][tn][1] + b1, 0.f);
            float v2 = fmaxf(acc[tm][tn][2] + b0, 0.f), v3 = fmaxf(acc[tm][tn][3] + b1, 0.f);
            if (r0 < M)     { float2 t = {v0, v1}; *(float2*)&C[(size_t)r0 * Nc + col] = t; }
            if (r0 + 8 < M) { float2 t = {v2, v3}; *(float2*)&C[(size_t)(r0 + 8) * Nc + col] = t; }
        }
    }
}

// ------------------------- edge projection (K=8) + split -------------------------
__global__ void k_eproj(const float* __restrict__ af, const float* __restrict__ W,
                        const float* __restrict__ b, float* __restrict__ eo) {
    size_t idx = (size_t)blockIdx.x * blockDim.x + threadIdx.x;
    if (idx < (size_t)Ee * Hh) {
        int c = (int)(idx & 255);
        size_t e = idx >> 8;
        float v = b[c];
#pragma unroll
        for (int k = 0; k < 8; k++) v += af[e * 8 + k] * W[k * Hh + c];
        eo[idx] = v;
        split_write(v, g_eh, g_el, idx);
    }
}

// ------------------------- per-layer edge/node kernels -------------------------
__global__ __launch_bounds__(256) void k_edge(float* __restrict__ Ce) {
    int c = threadIdx.x;
    int base = blockIdx.x * 32;
    float s = 0.f, sq = 0.f;
    for (int i = 0; i < 32; i++) {
        int e = base + i;
        int sN = g_src[e], dN = g_dst[e];
        float eh = g_ABDE[(size_t)dN * 1024 + 512 + c] +
                   g_ABDE[(size_t)sN * 1024 + 768 + c] +
                   Ce[(size_t)e * Hh + c];
        Ce[(size_t)e * Hh + c] = eh;
        float sg = 1.f / (1.f + expf(-eh));
        atomicAdd(&g_num[(size_t)dN * Hh + c], sg * g_ABDE[(size_t)sN * 1024 + 256 + c]);
        atomicAdd(&g_den[(size_t)dN * Hh + c], sg);
        s += eh; sq += eh * eh;
    }
    atomicAdd(&g_stats[2 * Hh + c], s);
    atomicAdd(&g_stats[3 * Hh + c], sq);
}

__global__ __launch_bounds__(256) void k_node() {
    int c = threadIdx.x;
    int base = blockIdx.x * 32;
    float s = 0.f, sq = 0.f;
    for (int i = 0; i < 32; i++) {
        int n = base + i;
        size_t o = (size_t)n * Hh + c;
        float xc = g_ABDE[(size_t)n * 1024 + c] + g_num[o] / (g_den[o] + AGG_EPS);
        g_num[o] = xc;
        s += xc; sq += xc * xc;
    }
    atomicAdd(&g_stats[c], s);
    atomicAdd(&g_stats[Hh + c], sq);
}

__global__ void k_apply_x(const float* __restrict__ xin, float* __restrict__ xout,
                          const float* __restrict__ gam, const float* __restrict__ bet) {
    size_t idx = (size_t)blockIdx.x * blockDim.x + threadIdx.x;
    if (idx < (size_t)Nn * Hh) {
        int c = (int)(idx & 255);
        float mu = g_stats[c] * (1.f / Nn);
        float var = g_stats[Hh + c] * (1.f / Nn) - mu * mu;
        float v = gam[c] * (g_num[idx] - mu) * rsqrtf(var + BN_EPS) + bet[c];
        float o = xin[idx] + fmaxf(v, 0.f);
        xout[idx] = o;
        split_write(o, g_xh, g_xl, idx);
    }
}

__global__ void k_apply_e(const float* __restrict__ ein, const float* __restrict__ ehat,
                          float* __restrict__ eout,
                          const float* __restrict__ gam, const float* __restrict__ bet) {
    size_t idx = (size_t)blockIdx.x * blockDim.x + threadIdx.x;
    if (idx < (size_t)Ee * Hh) {
        int c = (int)(idx & 255);
        float mu = g_stats[2 * Hh + c] * (1.f / Ee);
        float var = g_stats[3 * Hh + c] * (1.f / Ee) - mu * mu;
        float v = gam[c] * (ehat[idx] - mu) * rsqrtf(var + BN_EPS) + bet[c];
        float o = ein[idx] + fmaxf(v, 0.f);
        eout[idx] = o;
        split_write(o, g_eh, g_el, idx);
    }
}

// ------------------------- decoder-2 (H -> 1) -------------------------
__global__ void k_dec2(const float* __restrict__ h, const float* __restrict__ w2,
                       const float* __restrict__ b2, float* __restrict__ out) {
    int e = blockIdx.x * 8 + (threadIdx.x >> 5);
    int lane = threadIdx.x & 31;
    const float4* hp = (const float4*)(h + (size_t)e * Hh);
    const float4* wp = (const float4*)w2;
    float s = 0.f;
#pragma unroll
    for (int i = 0; i < 2; i++) {
        float4 hv = hp[lane * 2 + i];
        float4 wv = wp[lane * 2 + i];
        s += hv.x * wv.x + hv.y * wv.y + hv.z * wv.z + hv.w * wv.w;
    }
#pragma unroll
    for (int off = 16; off; off >>= 1) s += __shfl_xor_sync(0xFFFFFFFFu, s, off);
    if (lane == 0) out[e] = s + b2[0];
}

// ------------------------- host launcher -------------------------
extern "C" void kernel_launch(void* const* d_in, const int* in_sizes, int n_in,
                              void* d_out, int out_size)
{
    int wb = 3;
    for (int i = 3; i < n_in && i < 6; i++) {
        if (in_sizes[i] == 2 * Hh * Hh) { wb = i; break; }
    }

    const void*  eidx = d_in[0];
    const float* af   = (const float*)d_in[1];
    const float* hold = (const float*)d_in[2];
    const float* fw   = (const float*)d_in[wb + 0];
    const float* fb   = (const float*)d_in[wb + 1];
    const float* epw  = (const float*)d_in[wb + 2];
    const float* epb  = (const float*)d_in[wb + 3];
    const float* Aw   = (const float*)d_in[wb + 4];
    const float* Ab   = (const float*)d_in[wb + 5];
    const float* Bw   = (const float*)d_in[wb + 6];
    const float* Bb   = (const float*)d_in[wb + 7];
    const float* Cw   = (const float*)d_in[wb + 8];
    const float* Cb   = (const float*)d_in[wb + 9];
    const float* Dw   = (const float*)d_in[wb + 10];
    const float* Db   = (const float*)d_in[wb + 11];
    const float* Ew   = (const float*)d_in[wb + 12];
    const float* Eb   = (const float*)d_in[wb + 13];
    const float* bxg  = (const float*)d_in[wb + 14];
    const float* bxb  = (const float*)d_in[wb + 15];
    const float* beg  = (const float*)d_in[wb + 16];
    const float* beb  = (const float*)d_in[wb + 17];
    const float* d1w  = (const float*)d_in[wb + 18];
    const float* d1b  = (const float*)d_in[wb + 19];
    const float* d2w  = (const float*)d_in[wb + 20];
    const float* d2b  = (const float*)d_in[wb + 21];

    float *xA, *xB, *eA, *eB, *abde, *ce, *nump, *denp, *statsp, *bpackp, *fbiasp;
    __nv_bfloat16 *abde_hi, *abde_lo, *c_hi, *c_lo, *fw_hi, *fw_lo, *d1_hi, *d1_lo;
    __nv_bfloat16 *xh, *xl, *eh, *el, *hh, *hl;
    cudaGetSymbolAddress((void**)&xA, g_x);
    cudaGetSymbolAddress((void**)&xB, g_x2);
    cudaGetSymbolAddress((void**)&eA, g_e);
    cudaGetSymbolAddress((void**)&eB, g_e2);
    cudaGetSymbolAddress((void**)&abde, g_ABDE);
    cudaGetSymbolAddress((void**)&ce, g_Ce);
    cudaGetSymbolAddress((void**)&nump, g_num);
    cudaGetSymbolAddress((void**)&denp, g_den);
    cudaGetSymbolAddress((void**)&statsp, g_stats);
    cudaGetSymbolAddress((void**)&bpackp, g_bpack);
    cudaGetSymbolAddress((void**)&fbiasp, g_fbias);
    cudaGetSymbolAddress((void**)&abde_hi, g_abde_hi);
    cudaGetSymbolAddress((void**)&abde_lo, g_abde_lo);
    cudaGetSymbolAddress((void**)&c_hi, g_c_hi);
    cudaGetSymbolAddress((void**)&c_lo, g_c_lo);
    cudaGetSymbolAddress((void**)&fw_hi, g_fw_hi);
    cudaGetSymbolAddress((void**)&fw_lo, g_fw_lo);
    cudaGetSymbolAddress((void**)&d1_hi, g_d1_hi);
    cudaGetSymbolAddress((void**)&d1_lo, g_d1_lo);
    cudaGetSymbolAddress((void**)&xh, g_xh);
    cudaGetSymbolAddress((void**)&xl, g_xl);
    cudaGetSymbolAddress((void**)&eh, g_eh);
    cudaGetSymbolAddress((void**)&el, g_el);
    cudaGetSymbolAddress((void**)&hh, g_hh);
    cudaGetSymbolAddress((void**)&hl, g_hl);

    const int SMEM = 2 * ST_STRIDE;  // 64 KB
    cudaFuncSetAttribute(gemm_tc2<0>, cudaFuncAttributeMaxDynamicSharedMemorySize, SMEM);
    cudaFuncSetAttribute(gemm_tc2<1>, cudaFuncAttributeMaxDynamicSharedMemorySize, SMEM);
    cudaFuncSetAttribute(gemm_tc2<2>, cudaFuncAttributeMaxDynamicSharedMemorySize, SMEM);
    cudaFuncSetAttribute(gemm_dec1_tc, cudaFuncAttributeMaxDynamicSharedMemorySize, SMEM);

    // --- prep ---
    k_detect_idx<<<1, 256>>>((const unsigned int*)eidx);
    k_convert_idx<<<(Ee + 255) / 256, 256>>>(eidx);
    k_pack_b<<<(Ll * 4 * Hh + 255) / 256, 256>>>(Ab, Bb, Db, Eb);
    k_fbias<<<1, 256>>>(fw, fb);
    {
        size_t tw = (size_t)Ll * 1024 * 256;
        k_split_abde<<<(int)((tw + 255) / 256), 256>>>(Aw, Bw, Dw, Ew);
        k_split_gen<<<(256 * 256 + 255) / 256, 256>>>(fw + (size_t)Hh * Hh, fw_hi, fw_lo, 256, 256, 256);
        for (int l = 0; l < Ll; l++)
            k_split_gen<<<(256 * 256 + 255) / 256, 256>>>(Cw + (size_t)l * Hh * Hh,
                                                          c_hi + (size_t)l * Hh * Hh,
                                                          c_lo + (size_t)l * Hh * Hh, 256, 256, 256);
        k_split_gen<<<(256 * K_DEC + 255) / 256, 256>>>(d1w, d1_hi, d1_lo, 520, 256, K_DEC);
        size_t th = (size_t)Nn * Hh;
        k_split_plain<<<(int)((th + 255) / 256), 256>>>(hold, hh, hl, th);
        k_split_af<<<(int)(((size_t)Ee * 32 + 255) / 256), 256>>>(af);
    }

    // --- node fusion GEMM (writes x0 fp32 + hi/lo) + edge projection (writes e0 fp32 + hi/lo) ---
    {
        dim3 grid(Hh / 128, (Nn + 127) / 128);
        gemm_tc2<2><<<grid, 256, SMEM>>>(hh, hl, fw_hi, fw_lo, fbiasp, xA, xh, xl, Nn, Hh, Hh);
    }
    k_eproj<<<(int)(((size_t)Ee * Hh + 255) / 256), 256>>>(af, epw, epb, eA);

    float* xin = xA; float* xout = xB;
    float* ein = eA; float* eout = eB;

    for (int l = 0; l < Ll; l++) {
        cudaMemsetAsync(nump, 0, (size_t)Nn * Hh * sizeof(float));
        cudaMemsetAsync(denp, 0, (size_t)Nn * Hh * sizeof(float));
        cudaMemsetAsync(statsp, 0, 4 * Hh * sizeof(float));

        {   // fused A|B|D|E GEMM: [N,256] @ [256,1024]
            dim3 grid(4 * Hh / 128, (Nn + 127) / 128);
            gemm_tc2<0><<<grid, 256, SMEM>>>(xh, xl,
                                             abde_hi + (size_t)l * 1024 * 256,
                                             abde_lo + (size_t)l * 1024 * 256,
                                             bpackp + l * 4 * Hh, abde, nullptr, nullptr,
                                             Nn, Hh, 4 * Hh);
        }
        {   // Ce GEMM: [E,256] @ [256,256]
            dim3 grid(Hh / 128, (Ee + 127) / 128);
            gemm_tc2<0><<<grid, 256, SMEM>>>(eh, el,
                                             c_hi + (size_t)l * Hh * Hh,
                                             c_lo + (size_t)l * Hh * Hh,
                                             Cb + l * Hh, ce, nullptr, nullptr,
                                             Ee, Hh, Hh);
        }
        k_edge<<<Ee / 32, 256>>>(ce);
        k_node<<<Nn / 32, 256>>>();
        k_apply_x<<<(int)(((size_t)Nn * Hh + 255) / 256), 256>>>(xin, xout, bxg + l * Hh, bxb + l * Hh);
        if (l < Ll - 1)  // e is dead after the last layer
            k_apply_e<<<(int)(((size_t)Ee * Hh + 255) / 256), 256>>>(ein, ce, eout, beg + l * Hh, beb + l * Hh);

        float* t;
        t = xin; xin = xout; xout = t;
        t = ein; ein = eout; eout = t;
    }

    // --- decoder ---
    {
        dim3 grid(Hh / 128, (Ee + 127) / 128);
        gemm_dec1_tc<<<grid, 256, SMEM>>>(d1b, ce);
    }
    k_dec2<<<Ee / 8, 256>>>(ce, d2w, d2b, (float*)d_out);
}

// round 5
// speedup vs baseline: 2.0001x; 1.0095x over previous
#include <cuda_runtime.h>
#include <cuda_bf16.h>
#include <math.h>
#include <stdint.h>

// Problem constants
#define Hh 256
#define Ll 4
#define Nn 100000
#define Ee 300000
#define BN_EPS 1e-5f
#define AGG_EPS 1e-6f
#define K_DEC 544   // 520 padded to multiple of 32

// ------------------------- static device scratch -------------------------
__device__ float g_x[(size_t)Nn * Hh];
__device__ float g_x2[(size_t)Nn * Hh];
__device__ float g_e[(size_t)Ee * Hh];
__device__ float g_e2[(size_t)Ee * Hh];
__device__ float g_ABDE[(size_t)Nn * 4 * Hh];   // [N,1024]: A|B|D|E
__device__ float g_Ce[(size_t)Ee * Hh];         // e_hat -> decoder hidden
__device__ float g_num[(size_t)Nn * Hh];        // num -> xc (in-place)
__device__ float g_den[(size_t)Nn * Hh];
__device__ float g_stats[4 * Hh];               // sum_x, sumsq_x, sum_e, sumsq_e
__device__ float g_bpack[Ll * 4 * Hh];
__device__ float g_fbias[Hh];
__device__ int   g_src[Ee];
__device__ int   g_dst[Ee];
__device__ int   g_idx64;

// split bf16 weights, transposed to [N][K]
__device__ __nv_bfloat16 g_abde_hi[(size_t)Ll * 1024 * 256];
__device__ __nv_bfloat16 g_abde_lo[(size_t)Ll * 1024 * 256];
__device__ __nv_bfloat16 g_c_hi[(size_t)Ll * 256 * 256];
__device__ __nv_bfloat16 g_c_lo[(size_t)Ll * 256 * 256];
__device__ __nv_bfloat16 g_fw_hi[256 * 256];
__device__ __nv_bfloat16 g_fw_lo[256 * 256];
__device__ __nv_bfloat16 g_d1_hi[256 * K_DEC];
__device__ __nv_bfloat16 g_d1_lo[256 * K_DEC];

// split bf16 activations
__device__ __nv_bfloat16 g_xh[(size_t)Nn * Hh];
__device__ __nv_bfloat16 g_xl[(size_t)Nn * Hh];
__device__ __nv_bfloat16 g_eh[(size_t)Ee * Hh];
__device__ __nv_bfloat16 g_el[(size_t)Ee * Hh];
__device__ __nv_bfloat16 g_hh[(size_t)Nn * Hh];
__device__ __nv_bfloat16 g_hl[(size_t)Nn * Hh];
__device__ __nv_bfloat16 g_afh[(size_t)Ee * 32];
__device__ __nv_bfloat16 g_afl[(size_t)Ee * 32];

// ------------------------- small prep kernels -------------------------
__global__ void k_detect_idx(const unsigned int* __restrict__ w) {
    unsigned int s = 0;
    for (int i = threadIdx.x; i < 1024; i += 256) s |= w[2 * i + 1];
#pragma unroll
    for (int off = 16; off; off >>= 1) s |= __shfl_xor_sync(0xFFFFFFFFu, s, off);
    __shared__ unsigned int red[8];
    if ((threadIdx.x & 31) == 0) red[threadIdx.x >> 5] = s;
    __syncthreads();
    if (threadIdx.x == 0) {
        unsigned int t = 0;
        for (int i = 0; i < 8; i++) t |= red[i];
        g_idx64 = (t == 0u) ? 1 : 0;
    }
}

__global__ void k_convert_idx(const void* __restrict__ eidx) {
    int i = blockIdx.x * blockDim.x + threadIdx.x;
    if (i < Ee) {
        if (g_idx64) {
            const long long* p = (const long long*)eidx;
            g_src[i] = (int)p[i];
            g_dst[i] = (int)p[(size_t)Ee + i];
        } else {
            const int* p = (const int*)eidx;
            g_src[i] = p[i];
            g_dst[i] = p[Ee + i];
        }
    }
}

__device__ __forceinline__ void split_write(float v, __nv_bfloat16* hi, __nv_bfloat16* lo, size_t i) {
    __nv_bfloat16 h = __float2bfloat16_rn(v);
    hi[i] = h;
    lo[i] = __float2bfloat16_rn(v - __bfloat162float(h));
}

__global__ void k_split_abde(const float* __restrict__ Aw, const float* __restrict__ Bw,
                             const float* __restrict__ Dw, const float* __restrict__ Ew) {
    size_t i = (size_t)blockIdx.x * 256 + threadIdx.x;
    if (i < (size_t)Ll * 1024 * 256) {
        int k = (int)(i & 255);
        int n = (int)((i >> 8) & 1023);
        int l = (int)(i >> 18);
        const float* W = (n < 256) ? Aw : (n < 512) ? Bw : (n < 768) ? Dw : Ew;
        float v = W[(size_t)l * 65536 + (size_t)k * 256 + (n & 255)];
        split_write(v, g_abde_hi, g_abde_lo, i);
    }
}

__global__ void k_split_gen(const float* __restrict__ src, __nv_bfloat16* __restrict__ hi,
                            __nv_bfloat16* __restrict__ lo, int K, int N, int Kpad) {
    size_t i = (size_t)blockIdx.x * 256 + threadIdx.x;
    if (i < (size_t)N * Kpad) {
        int k = (int)(i % Kpad);
        int n = (int)(i / Kpad);
        float v = (k < K) ? src[(size_t)k * N + n] : 0.0f;
        split_write(v, hi, lo, i);
    }
}

__global__ void k_split_plain(const float* __restrict__ src, __nv_bfloat16* __restrict__ hi,
                              __nv_bfloat16* __restrict__ lo, size_t total) {
    size_t i = (size_t)blockIdx.x * 256 + threadIdx.x;
    if (i < total) split_write(src[i], hi, lo, i);
}

__global__ void k_split_af(const float* __restrict__ af) {
    size_t i = (size_t)blockIdx.x * 256 + threadIdx.x;
    if (i < (size_t)Ee * 32) {
        int c = (int)(i & 31);
        size_t e = i >> 5;
        float v = (c < 8) ? af[e * 8 + c] : 0.0f;
        split_write(v, g_afh, g_afl, i);
    }
}

__global__ void k_pack_b(const float* __restrict__ Ab, const float* __restrict__ Bb,
                         const float* __restrict__ Db, const float* __restrict__ Eb) {
    int i = blockIdx.x * blockDim.x + threadIdx.x;
    if (i < Ll * 4 * Hh) {
        int j4 = i % (4 * Hh);
        int l = i / (4 * Hh);
        int which = j4 >> 8;
        int j = j4 & 255;
        const float* B = (which == 0) ? Ab : (which == 1) ? Bb : (which == 2) ? Db : Eb;
        g_bpack[i] = B[l * Hh + j];
    }
}

__global__ void k_fbias(const float* __restrict__ fw, const float* __restrict__ fb) {
    int j = threadIdx.x;
    float s = fb[j];
    for (int k = 0; k < Hh; k++) s += fw[(size_t)k * Hh + j];
    g_fbias[j] = s;
}

// ------------------------- tensor-core machinery -------------------------
__device__ __forceinline__ void mma16816(float* c, const uint32_t* a, const uint32_t* b) {
    asm volatile(
        "mma.sync.aligned.m16n8k16.row.col.f32.bf16.bf16.f32 "
        "{%0,%1,%2,%3}, {%4,%5,%6,%7}, {%8,%9}, {%0,%1,%2,%3};"
        : "+f"(c[0]), "+f"(c[1]), "+f"(c[2]), "+f"(c[3])
        : "r"(a[0]), "r"(a[1]), "r"(a[2]), "r"(a[3]), "r"(b[0]), "r"(b[1]));
}
__device__ __forceinline__ void ldm_x4(uint32_t* r, uint32_t addr) {
    asm volatile("ldmatrix.sync.aligned.m8n8.x4.shared.b16 {%0,%1,%2,%3}, [%4];"
                 : "=r"(r[0]), "=r"(r[1]), "=r"(r[2]), "=r"(r[3]) : "r"(addr));
}
__device__ __forceinline__ void ldm_x2(uint32_t* r, uint32_t addr) {
    asm volatile("ldmatrix.sync.aligned.m8n8.x2.shared.b16 {%0,%1}, [%2];"
                 : "=r"(r[0]), "=r"(r[1]) : "r"(addr));
}
__device__ __forceinline__ void cpa16(uint32_t s, const void* g) {
    asm volatile("cp.async.cg.shared.global [%0], [%1], 16;" :: "r"(s), "l"(g));
}
__device__ __forceinline__ void cpa_commit() {
    asm volatile("cp.async.commit_group;");
}
__device__ __forceinline__ void cpa_wait0() {
    asm volatile("cp.async.wait_group 0;" ::: "memory");
}

__device__ __forceinline__ int sw_off(int row, int chunk) {
    return row * 64 + ((chunk ^ ((row >> 1) & 3)) << 4);
}

#define ST_ALO 8192
#define ST_BHI 16384
#define ST_BLO 24576
#define ST_STRIDE 32768

__device__ __forceinline__ void tile_compute(
    float acc[4][4][4], uint32_t sbase, int lane, int wr, int wc) {
    uint32_t sAhiB = sbase, sAloB = sbase + ST_ALO, sBhiB = sbase + ST_BHI, sBloB = sbase + ST_BLO;
#pragma unroll
    for (int kg = 0; kg < 2; kg++) {
        uint32_t ra[4][4], rbh[4][2], rbl[4][2];
#pragma unroll
        for (int tm = 0; tm < 4; tm++) {
            int row = wr * 64 + tm * 16 + (lane & 15);
            int ch = 2 * kg + (lane >> 4);
            ldm_x4(ra[tm], sAhiB + sw_off(row, ch));
        }
#pragma unroll
        for (int tn = 0; tn < 4; tn++) {
            int row = wc * 32 + tn * 8 + (lane & 7);
            int ch = 2 * kg + ((lane >> 3) & 1);
            uint32_t off = sw_off(row, ch);
            ldm_x2(rbh[tn], sBhiB + off);
            ldm_x2(rbl[tn], sBloB + off);
        }
#pragma unroll
        for (int tm = 0; tm < 4; tm++)
#pragma unroll
            for (int tn = 0; tn < 4; tn++) {
                mma16816(acc[tm][tn], ra[tm], rbh[tn]);
                mma16816(acc[tm][tn], ra[tm], rbl[tn]);
            }
#pragma unroll
        for (int tm = 0; tm < 4; tm++) {
            int row = wr * 64 + tm * 16 + (lane & 15);
            int ch = 2 * kg + (lane >> 4);
            ldm_x4(ra[tm], sAloB + sw_off(row, ch));
        }
#pragma unroll
        for (int tm = 0; tm < 4; tm++)
#pragma unroll
            for (int tn = 0; tn < 4; tn++)
                mma16816(acc[tm][tn], ra[tm], rbh[tn]);
    }
}

__device__ __forceinline__ uint32_t pack_bf2(float a, float b) {
    __nv_bfloat162 t = __floats2bfloat162_rn(a, b);
    return *(uint32_t*)&t;
}

// ------------------------- bf16x3 GEMM with cp.async pipeline -------------------------
// EPI: 0 = bias only; 1 = bias+relu; 2 = bias+relu + split-write bf16 hi/lo
template<int EPI>
__global__ __launch_bounds__(256) void gemm_tc2(
    const __nv_bfloat16* __restrict__ Ahi, const __nv_bfloat16* __restrict__ Alo,
    const __nv_bfloat16* __restrict__ Bhi, const __nv_bfloat16* __restrict__ Blo,
    const float* __restrict__ bias, float* __restrict__ C,
    __nv_bfloat16* __restrict__ Chi, __nv_bfloat16* __restrict__ Clo,
    int M, int K, int Nc)
{
    extern __shared__ __align__(16) char smem[];
    uint32_t sbase0 = (uint32_t)__cvta_generic_to_shared(smem);

    int tid = threadIdx.x, lane = tid & 31, w = tid >> 5;
    int wr = w >> 2, wc = w & 3;
    int bm = blockIdx.y * 128, bn = blockIdx.x * 128;

    int r = tid >> 1, ch0 = (tid & 1) * 2;
    int gr = bm + r; if (gr >= M) gr = M - 1;
    size_t aRow = (size_t)gr * K;
    size_t bRow = (size_t)(bn + r) * K;

    float acc[4][4][4];
#pragma unroll
    for (int i = 0; i < 4; i++)
#pragma unroll
        for (int j = 0; j < 4; j++)
#pragma unroll
            for (int q = 0; q < 4; q++) acc[i][j][q] = 0.f;

    auto load_stage = [&](uint32_t sb, int k0) {
#pragma unroll
        for (int i = 0; i < 2; i++) {
            int ch = ch0 + i;
            uint32_t so = sw_off(r, ch);
            size_t go = (size_t)k0 + ch * 8;
            cpa16(sb + so,          Ahi + aRow + go);
            cpa16(sb + ST_ALO + so, Alo + aRow + go);
            cpa16(sb + ST_BHI + so, Bhi + bRow + go);
            cpa16(sb + ST_BLO + so, Blo + bRow + go);
        }
        cpa_commit();
    };

    load_stage(sbase0, 0);
    int cur = 0;
    for (int k0 = 0; k0 < K; k0 += 32) {
        cpa_wait0();
        __syncthreads();
        if (k0 + 32 < K) load_stage(sbase0 + (cur ^ 1) * ST_STRIDE, k0 + 32);
        tile_compute(acc, sbase0 + cur * ST_STRIDE, lane, wr, wc);
        cur ^= 1;
    }

    int g = lane >> 2, tig = lane & 3;
#pragma unroll
    for (int tm = 0; tm < 4; tm++) {
        int r0 = bm + wr * 64 + tm * 16 + g;
#pragma unroll
        for (int tn = 0; tn < 4; tn++) {
            int col = bn + wc * 32 + tn * 8 + 2 * tig;
            float b0 = bias[col], b1 = bias[col + 1];
            float v0 = acc[tm][tn][0] + b0, v1 = acc[tm][tn][1] + b1;
            float v2 = acc[tm][tn][2] + b0, v3 = acc[tm][tn][3] + b1;
            if (EPI >= 1) {
                v0 = fmaxf(v0, 0.f); v1 = fmaxf(v1, 0.f);
                v2 = fmaxf(v2, 0.f); v3 = fmaxf(v3, 0.f);
            }
            if (r0 < M) {
                size_t o = (size_t)r0 * Nc + col;
                float2 t = {v0, v1}; *(float2*)&C[o] = t;
                if (EPI == 2) {
                    __nv_bfloat16 h0 = __float2bfloat16_rn(v0), h1 = __float2bfloat16_rn(v1);
                    *(uint32_t*)&Chi[o] = pack_bf2(v0, v1);
                    *(uint32_t*)&Clo[o] = pack_bf2(v0 - __bfloat162float(h0), v1 - __bfloat162float(h1));
                }
            }
            if (r0 + 8 < M) {
                size_t o = (size_t)(r0 + 8) * Nc + col;
                float2 t = {v2, v3}; *(float2*)&C[o] = t;
                if (EPI == 2) {
                    __nv_bfloat16 h2 = __float2bfloat16_rn(v2), h3 = __float2bfloat16_rn(v3);
                    *(uint32_t*)&Chi[o] = pack_bf2(v2, v3);
                    *(uint32_t*)&Clo[o] = pack_bf2(v2 - __bfloat162float(h2), v3 - __bfloat162float(h3));
                }
            }
        }
    }
}

// ------------------------- Ce GEMM with fused edge epilogue -------------------------
// Computes Ce = e @ C_w + C_b, then in-epilogue: e_hat = Ce + Dx[dst] + Ex[src],
// sigma = sigmoid(e_hat), REDG num/den, optional e_hat store + BN-e stats.
template<int WRITE_EH>
__global__ __launch_bounds__(256) void gemm_ce_fused(
    const __nv_bfloat16* __restrict__ Ahi, const __nv_bfloat16* __restrict__ Alo,
    const __nv_bfloat16* __restrict__ Bhi, const __nv_bfloat16* __restrict__ Blo,
    const float* __restrict__ bias, float* __restrict__ EHout)
{
    const int M = Ee, K = 256, Nc = 256;
    extern __shared__ __align__(16) char smem[];
    uint32_t sbase0 = (uint32_t)__cvta_generic_to_shared(smem);

    int tid = threadIdx.x, lane = tid & 31, w = tid >> 5;
    int wr = w >> 2, wc = w & 3;
    int bm = blockIdx.y * 128, bn = blockIdx.x * 128;

    int r = tid >> 1, ch0 = (tid & 1) * 2;
    int gr = bm + r; if (gr >= M) gr = M - 1;
    size_t aRow = (size_t)gr * K;
    size_t bRow = (size_t)(bn + r) * K;

    float acc[4][4][4];
#pragma unroll
    for (int i = 0; i < 4; i++)
#pragma unroll
        for (int j = 0; j < 4; j++)
#pragma unroll
            for (int q = 0; q < 4; q++) acc[i][j][q] = 0.f;

    auto load_stage = [&](uint32_t sb, int k0) {
#pragma unroll
        for (int i = 0; i < 2; i++) {
            int ch = ch0 + i;
            uint32_t so = sw_off(r, ch);
            size_t go = (size_t)k0 + ch * 8;
            cpa16(sb + so,          Ahi + aRow + go);
            cpa16(sb + ST_ALO + so, Alo + aRow + go);
            cpa16(sb + ST_BHI + so, Bhi + bRow + go);
            cpa16(sb + ST_BLO + so, Blo + bRow + go);
        }
        cpa_commit();
    };

    load_stage(sbase0, 0);
    int cur = 0;
    for (int k0 = 0; k0 < K; k0 += 32) {
        cpa_wait0();
        __syncthreads();
        if (k0 + 32 < K) load_stage(sbase0 + (cur ^ 1) * ST_STRIDE, k0 + 32);
        tile_compute(acc, sbase0 + cur * ST_STRIDE, lane, wr, wc);
        cur ^= 1;
    }

    int g = lane >> 2, tig = lane & 3;
    float ls[4][2], lq[4][2];
    if (WRITE_EH) {
#pragma unroll
        for (int tn = 0; tn < 4; tn++) { ls[tn][0] = ls[tn][1] = lq[tn][0] = lq[tn][1] = 0.f; }
    }

#pragma unroll
    for (int tm = 0; tm < 4; tm++) {
#pragma unroll
        for (int half = 0; half < 2; half++) {
            int e = bm + wr * 64 + tm * 16 + g + 8 * half;
            if (e < M) {
                int sN = g_src[e], dN = g_dst[e];
                const float* Drow = g_ABDE + (size_t)dN * 1024 + 512;
                const float* Erow = g_ABDE + (size_t)sN * 1024 + 768;
                const float* Brow = g_ABDE + (size_t)sN * 1024 + 256;
                float* nrow = g_num + (size_t)dN * Hh;
                float* drow = g_den + (size_t)dN * Hh;
#pragma unroll
                for (int tn = 0; tn < 4; tn++) {
                    int col = bn + wc * 32 + tn * 8 + 2 * tig;
                    float2 dv = *(const float2*)&Drow[col];
                    float2 ev = *(const float2*)&Erow[col];
                    float2 bv = *(const float2*)&Brow[col];
                    float eh0 = acc[tm][tn][2 * half + 0] + bias[col]     + dv.x + ev.x;
                    float eh1 = acc[tm][tn][2 * half + 1] + bias[col + 1] + dv.y + ev.y;
                    float sg0 = 1.f / (1.f + expf(-eh0));
                    float sg1 = 1.f / (1.f + expf(-eh1));
                    atomicAdd(&nrow[col],     sg0 * bv.x);
                    atomicAdd(&nrow[col + 1], sg1 * bv.y);
                    atomicAdd(&drow[col],     sg0);
                    atomicAdd(&drow[col + 1], sg1);
                    if (WRITE_EH) {
                        float2 t = {eh0, eh1};
                        *(float2*)&EHout[(size_t)e * Nc + col] = t;
                        ls[tn][0] += eh0; ls[tn][1] += eh1;
                        lq[tn][0] += eh0 * eh0; lq[tn][1] += eh1 * eh1;
                    }
                }
            }
        }
    }

    if (WRITE_EH) {
#pragma unroll
        for (int tn = 0; tn < 4; tn++) {
#pragma unroll
            for (int j = 0; j < 2; j++) {
                float v = ls[tn][j], q = lq[tn][j];
#pragma unroll
                for (int off = 4; off <= 16; off <<= 1) {
                    v += __shfl_xor_sync(0xFFFFFFFFu, v, off);
                    q += __shfl_xor_sync(0xFFFFFFFFu, q, off);
                }
                if (g == 0) {
                    int col = bn + wc * 32 + tn * 8 + 2 * tig + j;
                    atomicAdd(&g_stats[2 * Hh + col], v);
                    atomicAdd(&g_stats[3 * Hh + col], q);
                }
            }
        }
    }
}

// ------------------------- decoder-1 gather-GEMM (bf16x3, cp.async) -------------------------
__global__ __launch_bounds__(256) void gemm_dec1_tc(
    const float* __restrict__ bias, float* __restrict__ C)
{
    const int K = K_DEC, Nc = 256, M = Ee;
    extern __shared__ __align__(16) char smem[];
    uint32_t sbase0 = (uint32_t)__cvta_generic_to_shared(smem);

    int tid = threadIdx.x, lane = tid & 31, w = tid >> 5;
    int wr = w >> 2, wc = w & 3;
    int bm = blockIdx.y * 128, bn = blockIdx.x * 128;

    int r = tid >> 1, ch0 = (tid & 1) * 2;
    int e = bm + r; if (e >= M) e = M - 1;
    int sN = g_src[e], dN = g_dst[e];
    size_t bRow = (size_t)(bn + r) * K;

    float acc[4][4][4];
#pragma unroll
    for (int i = 0; i < 4; i++)
#pragma unroll
        for (int j = 0; j < 4; j++)
#pragma unroll
            for (int q = 0; q < 4; q++) acc[i][j][q] = 0.f;

    auto load_stage = [&](uint32_t sb, int k0) {
#pragma unroll
        for (int i = 0; i < 2; i++) {
            int ch = ch0 + i;
            uint32_t so = sw_off(r, ch);
            int c0 = k0 + ch * 8;
            const __nv_bfloat16 *ph, *pl;
            if (c0 < 256)      { ph = g_xh + (size_t)sN * Hh + c0;        pl = g_xl + (size_t)sN * Hh + c0; }
            else if (c0 < 512) { ph = g_xh + (size_t)dN * Hh + (c0-256);  pl = g_xl + (size_t)dN * Hh + (c0-256); }
            else               { ph = g_afh + (size_t)e * 32 + (c0-512);  pl = g_afl + (size_t)e * 32 + (c0-512); }
            cpa16(sb + so,          ph);
            cpa16(sb + ST_ALO + so, pl);
            cpa16(sb + ST_BHI + so, g_d1_hi + bRow + c0);
            cpa16(sb + ST_BLO + so, g_d1_lo + bRow + c0);
        }
        cpa_commit();
    };

    load_stage(sbase0, 0);
    int cur = 0;
    for (int k0 = 0; k0 < K; k0 += 32) {
        cpa_wait0();
        __syncthreads();
        if (k0 + 32 < K) load_stage(sbase0 + (cur ^ 1) * ST_STRIDE, k0 + 32);
        tile_compute(acc, sbase0 + cur * ST_STRIDE, lane, wr, wc);
        cur ^= 1;
    }

    int g = lane >> 2, tig = lane & 3;
#pragma unroll
    for (int tm = 0; tm < 4; tm++) {
        int r0 = bm + wr * 64 + tm * 16 + g;
#pragma unroll
        for (int tn = 0; tn < 4; tn++) {
            int col = bn + wc * 32 + tn * 8 + 2 * tig;
            float b0 = bias[col], b1 = bias[col + 1];
            float v0 = fmaxf(acc[tm][tn][0] + b0, 0.f), v1 = fmaxf(acc[tm][tn][1] + b1, 0.f);
            float v2 = fmaxf(acc[tm][tn][2] + b0, 0.f), v3 = fmaxf(acc[tm][tn][3] + b1, 0.f);
            if (r0 < M)     { float2 t = {v0, v1}; *(float2*)&C[(size_t)r0 * Nc + col] = t; }
            if (r0 + 8 < M) { float2 t = {v2, v3}; *(float2*)&C[(size_t)(r0 + 8) * Nc + col] = t; }
        }
    }
}

// ------------------------- edge projection (K=8) + split -------------------------
__global__ void k_eproj(const float* __restrict__ af, const float* __restrict__ W,
                        const float* __restrict__ b, float* __restrict__ eo) {
    size_t idx = (size_t)blockIdx.x * blockDim.x + threadIdx.x;
    if (idx < (size_t)Ee * Hh) {
        int c = (int)(idx & 255);
        size_t e = idx >> 8;
        float v = b[c];
#pragma unroll
        for (int k = 0; k < 8; k++) v += af[e * 8 + k] * W[k * Hh + c];
        eo[idx] = v;
        split_write(v, g_eh, g_el, idx);
    }
}

// ------------------------- per-layer node kernels -------------------------
__global__ __launch_bounds__(256) void k_node() {
    int c = threadIdx.x;
    int base = blockIdx.x * 32;
    float s = 0.f, sq = 0.f;
    for (int i = 0; i < 32; i++) {
        int n = base + i;
        size_t o = (size_t)n * Hh + c;
        float xc = g_ABDE[(size_t)n * 1024 + c] + g_num[o] / (g_den[o] + AGG_EPS);
        g_num[o] = xc;
        s += xc; sq += xc * xc;
    }
    atomicAdd(&g_stats[c], s);
    atomicAdd(&g_stats[Hh + c], sq);
}

__global__ void k_apply_x(const float* __restrict__ xin, float* __restrict__ xout,
                          const float* __restrict__ gam, const float* __restrict__ bet) {
    size_t idx = (size_t)blockIdx.x * blockDim.x + threadIdx.x;
    if (idx < (size_t)Nn * Hh) {
        int c = (int)(idx & 255);
        float mu = g_stats[c] * (1.f / Nn);
        float var = g_stats[Hh + c] * (1.f / Nn) - mu * mu;
        float v = gam[c] * (g_num[idx] - mu) * rsqrtf(var + BN_EPS) + bet[c];
        float o = xin[idx] + fmaxf(v, 0.f);
        xout[idx] = o;
        split_write(o, g_xh, g_xl, idx);
    }
}

__global__ void k_apply_e(const float* __restrict__ ein, const float* __restrict__ ehat,
                          float* __restrict__ eout,
                          const float* __restrict__ gam, const float* __restrict__ bet) {
    size_t idx = (size_t)blockIdx.x * blockDim.x + threadIdx.x;
    if (idx < (size_t)Ee * Hh) {
        int c = (int)(idx & 255);
        float mu = g_stats[2 * Hh + c] * (1.f / Ee);
        float var = g_stats[3 * Hh + c] * (1.f / Ee) - mu * mu;
        float v = gam[c] * (ehat[idx] - mu) * rsqrtf(var + BN_EPS) + bet[c];
        float o = ein[idx] + fmaxf(v, 0.f);
        eout[idx] = o;
        split_write(o, g_eh, g_el, idx);
    }
}

// ------------------------- decoder-2 (H -> 1) -------------------------
__global__ void k_dec2(const float* __restrict__ h, const float* __restrict__ w2,
                       const float* __restrict__ b2, float* __restrict__ out) {
    int e = blockIdx.x * 8 + (threadIdx.x >> 5);
    int lane = threadIdx.x & 31;
    const float4* hp = (const float4*)(h + (size_t)e * Hh);
    const float4* wp = (const float4*)w2;
    float s = 0.f;
#pragma unroll
    for (int i = 0; i < 2; i++) {
        float4 hv = hp[lane * 2 + i];
        float4 wv = wp[lane * 2 + i];
        s += hv.x * wv.x + hv.y * wv.y + hv.z * wv.z + hv.w * wv.w;
    }
#pragma unroll
    for (int off = 16; off; off >>= 1) s += __shfl_xor_sync(0xFFFFFFFFu, s, off);
    if (lane == 0) out[e] = s + b2[0];
}

// ------------------------- host launcher -------------------------
extern "C" void kernel_launch(void* const* d_in, const int* in_sizes, int n_in,
                              void* d_out, int out_size)
{
    int wb = 3;
    for (int i = 3; i < n_in && i < 6; i++) {
        if (in_sizes[i] == 2 * Hh * Hh) { wb = i; break; }
    }

    const void*  eidx = d_in[0];
    const float* af   = (const float*)d_in[1];
    const float* hold = (const float*)d_in[2];
    const float* fw   = (const float*)d_in[wb + 0];
    const float* fb   = (const float*)d_in[wb + 1];
    const float* epw  = (const float*)d_in[wb + 2];
    const float* epb  = (const float*)d_in[wb + 3];
    const float* Aw   = (const float*)d_in[wb + 4];
    const float* Ab   = (const float*)d_in[wb + 5];
    const float* Bw   = (const float*)d_in[wb + 6];
    const float* Bb   = (const float*)d_in[wb + 7];
    const float* Cw   = (const float*)d_in[wb + 8];
    const float* Cb   = (const float*)d_in[wb + 9];
    const float* Dw   = (const float*)d_in[wb + 10];
    const float* Db   = (const float*)d_in[wb + 11];
    const float* Ew   = (const float*)d_in[wb + 12];
    const float* Eb   = (const float*)d_in[wb + 13];
    const float* bxg  = (const float*)d_in[wb + 14];
    const float* bxb  = (const float*)d_in[wb + 15];
    const float* beg  = (const float*)d_in[wb + 16];
    const float* beb  = (const float*)d_in[wb + 17];
    const float* d1w  = (const float*)d_in[wb + 18];
    const float* d1b  = (const float*)d_in[wb + 19];
    const float* d2w  = (const float*)d_in[wb + 20];
    const float* d2b  = (const float*)d_in[wb + 21];

    float *xA, *xB, *eA, *eB, *abde, *ce, *nump, *denp, *statsp, *bpackp, *fbiasp;
    __nv_bfloat16 *abde_hi, *abde_lo, *c_hi, *c_lo, *fw_hi, *fw_lo, *d1_hi, *d1_lo;
    __nv_bfloat16 *xh, *xl, *eh, *el, *hh, *hl;
    cudaGetSymbolAddress((void**)&xA, g_x);
    cudaGetSymbolAddress((void**)&xB, g_x2);
    cudaGetSymbolAddress((void**)&eA, g_e);
    cudaGetSymbolAddress((void**)&eB, g_e2);
    cudaGetSymbolAddress((void**)&abde, g_ABDE);
    cudaGetSymbolAddress((void**)&ce, g_Ce);
    cudaGetSymbolAddress((void**)&nump, g_num);
    cudaGetSymbolAddress((void**)&denp, g_den);
    cudaGetSymbolAddress((void**)&statsp, g_stats);
    cudaGetSymbolAddress((void**)&bpackp, g_bpack);
    cudaGetSymbolAddress((void**)&fbiasp, g_fbias);
    cudaGetSymbolAddress((void**)&abde_hi, g_abde_hi);
    cudaGetSymbolAddress((void**)&abde_lo, g_abde_lo);
    cudaGetSymbolAddress((void**)&c_hi, g_c_hi);
    cudaGetSymbolAddress((void**)&c_lo, g_c_lo);
    cudaGetSymbolAddress((void**)&fw_hi, g_fw_hi);
    cudaGetSymbolAddress((void**)&fw_lo, g_fw_lo);
    cudaGetSymbolAddress((void**)&d1_hi, g_d1_hi);
    cudaGetSymbolAddress((void**)&d1_lo, g_d1_lo);
    cudaGetSymbolAddress((void**)&xh, g_xh);
    cudaGetSymbolAddress((void**)&xl, g_xl);
    cudaGetSymbolAddress((void**)&eh, g_eh);
    cudaGetSymbolAddress((void**)&el, g_el);
    cudaGetSymbolAddress((void**)&hh, g_hh);
    cudaGetSymbolAddress((void**)&hl, g_hl);

    const int SMEM = 2 * ST_STRIDE;  // 64 KB
    cudaFuncSetAttribute(gemm_tc2<0>, cudaFuncAttributeMaxDynamicSharedMemorySize, SMEM);
    cudaFuncSetAttribute(gemm_tc2<1>, cudaFuncAttributeMaxDynamicSharedMemorySize, SMEM);
    cudaFuncSetAttribute(gemm_tc2<2>, cudaFuncAttributeMaxDynamicSharedMemorySize, SMEM);
    cudaFuncSetAttribute(gemm_ce_fused<0>, cudaFuncAttributeMaxDynamicSharedMemorySize, SMEM);
    cudaFuncSetAttribute(gemm_ce_fused<1>, cudaFuncAttributeMaxDynamicSharedMemorySize, SMEM);
    cudaFuncSetAttribute(gemm_dec1_tc, cudaFuncAttributeMaxDynamicSharedMemorySize, SMEM);

    // --- prep ---
    k_detect_idx<<<1, 256>>>((const unsigned int*)eidx);
    k_convert_idx<<<(Ee + 255) / 256, 256>>>(eidx);
    k_pack_b<<<(Ll * 4 * Hh + 255) / 256, 256>>>(Ab, Bb, Db, Eb);
    k_fbias<<<1, 256>>>(fw, fb);
    {
        size_t tw = (size_t)Ll * 1024 * 256;
        k_split_abde<<<(int)((tw + 255) / 256), 256>>>(Aw, Bw, Dw, Ew);
        k_split_gen<<<(256 * 256 + 255) / 256, 256>>>(fw + (size_t)Hh * Hh, fw_hi, fw_lo, 256, 256, 256);
        for (int l = 0; l < Ll; l++)
            k_split_gen<<<(256 * 256 + 255) / 256, 256>>>(Cw + (size_t)l * Hh * Hh,
                                                          c_hi + (size_t)l * Hh * Hh,
                                                          c_lo + (size_t)l * Hh * Hh, 256, 256, 256);
        k_split_gen<<<(256 * K_DEC + 255) / 256, 256>>>(d1w, d1_hi, d1_lo, 520, 256, K_DEC);
        size_t th = (size_t)Nn * Hh;
        k_split_plain<<<(int)((th + 255) / 256), 256>>>(hold, hh, hl, th);
        k_split_af<<<(int)(((size_t)Ee * 32 + 255) / 256), 256>>>(af);
    }

    // --- node fusion GEMM + edge projection ---
    {
        dim3 grid(Hh / 128, (Nn + 127) / 128);
        gemm_tc2<2><<<grid, 256, SMEM>>>(hh, hl, fw_hi, fw_lo, fbiasp, xA, xh, xl, Nn, Hh, Hh);
    }
    k_eproj<<<(int)(((size_t)Ee * Hh + 255) / 256), 256>>>(af, epw, epb, eA);

    float* xin = xA; float* xout = xB;
    float* ein = eA; float* eout = eB;

    for (int l = 0; l < Ll; l++) {
        cudaMemsetAsync(nump, 0, (size_t)Nn * Hh * sizeof(float));
        cudaMemsetAsync(denp, 0, (size_t)Nn * Hh * sizeof(float));
        cudaMemsetAsync(statsp, 0, 4 * Hh * sizeof(float));

        {   // fused A|B|D|E GEMM: [N,256] @ [256,1024]
            dim3 grid(4 * Hh / 128, (Nn + 127) / 128);
            gemm_tc2<0><<<grid, 256, SMEM>>>(xh, xl,
                                             abde_hi + (size_t)l * 1024 * 256,
                                             abde_lo + (size_t)l * 1024 * 256,
                                             bpackp + l * 4 * Hh, abde, nullptr, nullptr,
                                             Nn, Hh, 4 * Hh);
        }
        {   // Ce GEMM + fused edge phase
            dim3 grid(2, (Ee + 127) / 128);
            if (l < Ll - 1)
                gemm_ce_fused<1><<<grid, 256, SMEM>>>(eh, el,
                                                      c_hi + (size_t)l * Hh * Hh,
                                                      c_lo + (size_t)l * Hh * Hh,
                                                      Cb + l * Hh, ce);
            else
                gemm_ce_fused<0><<<grid, 256, SMEM>>>(eh, el,
                                                      c_hi + (size_t)l * Hh * Hh,
                                                      c_lo + (size_t)l * Hh * Hh,
                                                      Cb + l * Hh, ce);
        }
        k_node<<<Nn / 32, 256>>>();
        k_apply_x<<<(int)(((size_t)Nn * Hh + 255) / 256), 256>>>(xin, xout, bxg + l * Hh, bxb + l * Hh);
        if (l < Ll - 1)  // e is dead after the last layer
            k_apply_e<<<(int)(((size_t)Ee * Hh + 255) / 256), 256>>>(ein, ce, eout, beg + l * Hh, beb + l * Hh);

        float* t;
        t = xin; xin = xout; xout = t;
        t = ein; ein = eout; eout = t;
    }

    // --- decoder ---
    {
        dim3 grid(Hh / 128, (Ee + 127) / 128);
        gemm_dec1_tc<<<grid, 256, SMEM>>>(d1b, ce);
    }
    k_dec2<<<Ee / 8, 256>>>(ce, d2w, d2b, (float*)d_out);
}